// round 2
// baseline (speedup 1.0000x reference)
#include <cuda_runtime.h>

#define BATCH 2
#define SEQ   2048
#define DIM   2048
#define NH    16
#define NKV   4
#define HD    128
#define KVDIM (NKV*HD)      // 512
#define MS    (BATCH*SEQ)   // 4096

// Scratch (device globals — no allocation allowed)
__device__ float g_q[MS * DIM];
__device__ float g_k[MS * KVDIM];
__device__ float g_v[MS * KVDIM];
__device__ float g_att[MS * DIM];

// ---------------------------------------------------------------------------
// SGEMM: C[M,N] = A[M,K] @ B[K,N], all row-major. 128x128 block, BK=16,
// 256 threads, 8x8 micro-tile (split 4+4 for conflict-friendly smem reads).
// M,N multiples of 128; K multiple of 16.
// ---------------------------------------------------------------------------
__global__ __launch_bounds__(256) void sgemm_k(const float* __restrict__ A,
                                               const float* __restrict__ B,
                                               float* __restrict__ C,
                                               int M, int N, int K)
{
    __shared__ float As[16][132];
    __shared__ float Bs[16][132];

    int tid = threadIdx.x;
    int tx = tid & 15, ty = tid >> 4;
    int bm = blockIdx.y << 7;
    int bn = blockIdx.x << 7;

    float acc[8][8];
#pragma unroll
    for (int i = 0; i < 8; i++)
#pragma unroll
        for (int j = 0; j < 8; j++) acc[i][j] = 0.f;

    for (int k0 = 0; k0 < K; k0 += 16) {
        // A tile: 128 rows x 16 k  (store transposed As[k][m])
#pragma unroll
        for (int l = 0; l < 2; l++) {
            int i4 = tid + l * 256;            // 0..511 float4 index
            int row = i4 >> 2;                 // 4 float4 per row
            int kc  = (i4 & 3) << 2;
            float4 v = *(const float4*)(A + (size_t)(bm + row) * K + k0 + kc);
            As[kc + 0][row] = v.x;
            As[kc + 1][row] = v.y;
            As[kc + 2][row] = v.z;
            As[kc + 3][row] = v.w;
        }
        // B tile: 16 k x 128 cols
#pragma unroll
        for (int l = 0; l < 2; l++) {
            int i4 = tid + l * 256;
            int kr = i4 >> 5;                  // 32 float4 per k-row
            int nc = (i4 & 31) << 2;
            *(float4*)&Bs[kr][nc] =
                *(const float4*)(B + (size_t)(k0 + kr) * N + bn + nc);
        }
        __syncthreads();

#pragma unroll
        for (int kk = 0; kk < 16; kk++) {
            float a[8], b[8];
#pragma unroll
            for (int i = 0; i < 4; i++) {
                a[i]     = As[kk][ty * 4 + i];
                a[4 + i] = As[kk][64 + ty * 4 + i];
            }
#pragma unroll
            for (int j = 0; j < 4; j++) {
                b[j]     = Bs[kk][tx * 4 + j];
                b[4 + j] = Bs[kk][64 + tx * 4 + j];
            }
#pragma unroll
            for (int i = 0; i < 8; i++)
#pragma unroll
                for (int j = 0; j < 8; j++) acc[i][j] += a[i] * b[j];
        }
        __syncthreads();
    }

#pragma unroll
    for (int i = 0; i < 8; i++) {
        int r = bm + (i >> 2) * 64 + ty * 4 + (i & 3);
#pragma unroll
        for (int jc = 0; jc < 2; jc++) {
            float4 v = make_float4(acc[i][jc * 4 + 0], acc[i][jc * 4 + 1],
                                   acc[i][jc * 4 + 2], acc[i][jc * 4 + 3]);
            *(float4*)(C + (size_t)r * N + bn + jc * 64 + tx * 4) = v;
        }
    }
}

// ---------------------------------------------------------------------------
// RoPE (in-place): data layout [B*S, nheads*HD]; pair p rotates cols 2p,2p+1
// with cos/sin[s][p].
// ---------------------------------------------------------------------------
__global__ void rope_k(float* __restrict__ d, const float* __restrict__ c,
                       const float* __restrict__ s, int nheads)
{
    int idx = blockIdx.x * blockDim.x + threadIdx.x;
    int total = MS * nheads * (HD / 2);
    if (idx >= total) return;
    int p  = idx & 63;
    int h  = (idx >> 6) % nheads;
    int bs = idx / (64 * nheads);
    int sq = bs & (SEQ - 1);
    float cv = c[sq * 64 + p];
    float sv = s[sq * 64 + p];
    float* base = d + (size_t)bs * nheads * HD + h * HD + 2 * p;
    float xr = base[0], xi = base[1];
    base[0] = xr * cv - xi * sv;
    base[1] = xr * sv + xi * cv;
}

// ---------------------------------------------------------------------------
// Flash attention (causal, GQA). One block = (64 query rows, one (b,h)).
// 256 threads as 16x16; 4x4 score micro-tile; online softmax; O in regs
// (4 rows x 8 cols per thread). K staged transposed in smem for
// conflict-free QK^T inner reads.
// ---------------------------------------------------------------------------
__global__ __launch_bounds__(256) void attn_k(const float* __restrict__ Q,
                                              const float* __restrict__ Kg,
                                              const float* __restrict__ Vg,
                                              float* __restrict__ O)
{
    extern __shared__ float sm[];
    float* Qs   = sm;                 // [64][132]
    float* Kst  = Qs  + 64 * 132;     // [128][65]  (transposed: [d][key])
    float* Vs   = Kst + 128 * 65;     // [64][132]
    float* Sc   = Vs  + 64 * 132;     // [64][68]
    float* lrow = Sc  + 64 * 68;      // [64]
    float* crow = lrow + 64;          // [64]

    int tid = threadIdx.x;
    int tx = tid & 15, ty = tid >> 4;
    int mblk = blockIdx.x;
    int bh = blockIdx.y;
    int b = bh >> 4, h = bh & 15;
    int g = h >> 2;                   // kv head
    int m0 = mblk * 64;
    const float scale = 0.08838834764831845f;  // 1/sqrt(128)

    // Load Q tile (64 x 128)
    const float* qbase = Q + ((size_t)(b * SEQ + m0)) * DIM + h * HD;
#pragma unroll
    for (int l = 0; l < 8; l++) {
        int i4 = tid + l * 256;
        int row = i4 >> 5;
        int dc  = (i4 & 31) << 2;
        *(float4*)&Qs[row * 132 + dc] =
            *(const float4*)(qbase + (size_t)row * DIM + dc);
    }

    float oacc[4][8];
#pragma unroll
    for (int i = 0; i < 4; i++)
#pragma unroll
        for (int c = 0; c < 8; c++) oacc[i][c] = 0.f;

    float mreg = -1e30f, lreg = 0.f;  // valid for tid < 64 (row = tid)

    const float* kbase = Kg + (size_t)(b * SEQ) * KVDIM + g * HD;
    const float* vbase = Vg + (size_t)(b * SEQ) * KVDIM + g * HD;

    for (int n0 = 0; n0 <= m0; n0 += 64) {
        __syncthreads();  // previous iteration's Sc/Vs consumers done
        // Load K (transposed) and V tiles
#pragma unroll
        for (int l = 0; l < 8; l++) {
            int i4 = tid + l * 256;
            int row = i4 >> 5;
            int dc  = (i4 & 31) << 2;
            float4 kv = *(const float4*)(kbase + (size_t)(n0 + row) * KVDIM + dc);
            Kst[(dc + 0) * 65 + row] = kv.x;
            Kst[(dc + 1) * 65 + row] = kv.y;
            Kst[(dc + 2) * 65 + row] = kv.z;
            Kst[(dc + 3) * 65 + row] = kv.w;
            *(float4*)&Vs[row * 132 + dc] =
                *(const float4*)(vbase + (size_t)(n0 + row) * KVDIM + dc);
        }
        __syncthreads();

        // S = Q K^T (4x4 per thread)
        float sacc[4][4];
#pragma unroll
        for (int i = 0; i < 4; i++)
#pragma unroll
            for (int j = 0; j < 4; j++) sacc[i][j] = 0.f;

        for (int d = 0; d < HD; d++) {
            float a[4], kq[4];
#pragma unroll
            for (int i = 0; i < 4; i++) a[i]  = Qs[(ty * 4 + i) * 132 + d];
#pragma unroll
            for (int j = 0; j < 4; j++) kq[j] = Kst[d * 65 + tx * 4 + j];
#pragma unroll
            for (int i = 0; i < 4; i++)
#pragma unroll
                for (int j = 0; j < 4; j++) sacc[i][j] += a[i] * kq[j];
        }

        // scale + causal mask + stage to smem
#pragma unroll
        for (int i = 0; i < 4; i++) {
            int qi = m0 + ty * 4 + i;
#pragma unroll
            for (int j = 0; j < 4; j++) {
                int kj = n0 + tx * 4 + j;
                float v = (kj <= qi) ? sacc[i][j] * scale : -1e30f;
                Sc[(ty * 4 + i) * 68 + tx * 4 + j] = v;
            }
        }
        __syncthreads();

        // Online softmax: thread tid (<64) owns row tid
        if (tid < 64) {
            float rm = -1e30f;
            for (int j = 0; j < 64; j++) rm = fmaxf(rm, Sc[tid * 68 + j]);
            float nm = fmaxf(mreg, rm);
            float cf = __expf(mreg - nm);
            float sum = 0.f;
            for (int j = 0; j < 64; j++) {
                float p = __expf(Sc[tid * 68 + j] - nm);
                Sc[tid * 68 + j] = p;
                sum += p;
            }
            lreg = lreg * cf + sum;
            mreg = nm;
            crow[tid] = cf;
            lrow[tid] = lreg;
        }
        __syncthreads();

        // O = O*corr + P V
#pragma unroll
        for (int i = 0; i < 4; i++) {
            float cf = crow[ty * 4 + i];
#pragma unroll
            for (int c = 0; c < 8; c++) oacc[i][c] *= cf;
        }
        for (int j = 0; j < 64; j++) {
            float p[4];
#pragma unroll
            for (int i = 0; i < 4; i++) p[i] = Sc[(ty * 4 + i) * 68 + j];
            float4 v0 = *(float4*)&Vs[j * 132 + tx * 4];
            float4 v1 = *(float4*)&Vs[j * 132 + 64 + tx * 4];
            float vv[8] = {v0.x, v0.y, v0.z, v0.w, v1.x, v1.y, v1.z, v1.w};
#pragma unroll
            for (int i = 0; i < 4; i++)
#pragma unroll
                for (int c = 0; c < 8; c++) oacc[i][c] += p[i] * vv[c];
        }
    }

    // Finalize: divide by l, write out (layout [b*S+q][h*HD + d])
#pragma unroll
    for (int i = 0; i < 4; i++) {
        float inv = 1.f / lrow[ty * 4 + i];
        int qi = m0 + ty * 4 + i;
        float* obase = O + ((size_t)(b * SEQ + qi)) * DIM + h * HD;
        float4 w0 = make_float4(oacc[i][0] * inv, oacc[i][1] * inv,
                                oacc[i][2] * inv, oacc[i][3] * inv);
        float4 w1 = make_float4(oacc[i][4] * inv, oacc[i][5] * inv,
                                oacc[i][6] * inv, oacc[i][7] * inv);
        *(float4*)(obase + tx * 4) = w0;
        *(float4*)(obase + 64 + tx * 4) = w1;
    }
}

// ---------------------------------------------------------------------------
extern "C" void kernel_launch(void* const* d_in, const int* in_sizes, int n_in,
                              void* d_out, int out_size)
{
    const float* x  = (const float*)d_in[0];
    const float* fc = (const float*)d_in[1];
    const float* fs = (const float*)d_in[2];
    const float* Wq = (const float*)d_in[3];
    const float* Wk = (const float*)d_in[4];
    const float* Wv = (const float*)d_in[5];
    const float* Wo = (const float*)d_in[6];
    float* out = (float*)d_out;

    float *q, *k, *v, *att;
    cudaGetSymbolAddress((void**)&q,   g_q);
    cudaGetSymbolAddress((void**)&k,   g_k);
    cudaGetSymbolAddress((void**)&v,   g_v);
    cudaGetSymbolAddress((void**)&att, g_att);

    // Projections
    sgemm_k<<<dim3(DIM / 128,   MS / 128), 256>>>(x, Wq, q,   MS, DIM,   DIM);
    sgemm_k<<<dim3(KVDIM / 128, MS / 128), 256>>>(x, Wk, k,   MS, KVDIM, DIM);
    sgemm_k<<<dim3(KVDIM / 128, MS / 128), 256>>>(x, Wv, v,   MS, KVDIM, DIM);

    // RoPE
    rope_k<<<(MS * NH  * 64 + 255) / 256, 256>>>(q, fc, fs, NH);
    rope_k<<<(MS * NKV * 64 + 255) / 256, 256>>>(k, fc, fs, NKV);

    // Attention
    int smem = (64 * 132 + 128 * 65 + 64 * 132 + 64 * 68 + 128) * sizeof(float);
    cudaFuncSetAttribute(attn_k, cudaFuncAttributeMaxDynamicSharedMemorySize, smem);
    attn_k<<<dim3(SEQ / 64, BATCH * NH), 256, smem>>>(q, k, v, att);

    // Output projection
    sgemm_k<<<dim3(DIM / 128, MS / 128), 256>>>(att, Wo, out, MS, DIM, DIM);
}

// round 7
// speedup vs baseline: 1.6828x; 1.6828x over previous
#include <cuda_runtime.h>
#include <cstdint>

#define BATCH 2
#define SEQ   2048
#define DIM   2048
#define NH    16
#define NKV   4
#define HD    128
#define KVDIM (NKV*HD)      // 512
#define MS    (BATCH*SEQ)   // 4096

// Scratch (device globals — no allocation allowed)
__device__ float g_q[MS * DIM];
__device__ float g_k[MS * KVDIM];
__device__ float g_v[MS * KVDIM];
__device__ float g_att[MS * DIM];

// ===========================================================================
// tf32 mma.sync GEMM (base-ISA sm_103; tcgen05 unavailable at this target)
// C[M,N] = A[M,K] @ B[K,N], row-major. CTA 128x128, BK=32, 256 thr, 8 warps
// (2x4), warp tile 64x32 = 4x4 of m16n8k8. Double-buffered smem, LDG->cvt.rna
// ->STS staging.
// ===========================================================================
#define BM 128
#define BN 128
#define BK 32
#define ASTR 36     // A smem row stride (floats): bank = (4g+c)%32 unique
#define BSTR 136    // B smem row stride (floats): bank = (8c+g)%32 unique
#define ABUF (BM*ASTR)          // 4608 floats
#define BBUF (BK*BSTR)          // 4352 floats
#define GSMEM ((2*ABUF + 2*BBUF) * 4)   // 71680 bytes

__device__ __forceinline__ uint32_t f2tf32(float f) {
    uint32_t r;
    asm("cvt.rna.tf32.f32 %0, %1;" : "=r"(r) : "f"(f));
    return r;
}

__device__ __forceinline__ void mma_tf32(float* c, const uint32_t* a,
                                         const uint32_t* b) {
    asm volatile(
        "mma.sync.aligned.m16n8k8.row.col.f32.tf32.tf32.f32 "
        "{%0,%1,%2,%3}, {%4,%5,%6,%7}, {%8,%9}, {%0,%1,%2,%3};"
        : "+f"(c[0]), "+f"(c[1]), "+f"(c[2]), "+f"(c[3])
        : "r"(a[0]), "r"(a[1]), "r"(a[2]), "r"(a[3]), "r"(b[0]), "r"(b[1]));
}

__device__ __forceinline__ void gemm_core(const float* __restrict__ A,
                                          const float* __restrict__ B,
                                          float* __restrict__ C,
                                          int N, int K, int bm, int bn)
{
    extern __shared__ float sm[];
    float* As = sm;                // [2][ABUF]
    float* Bs = sm + 2 * ABUF;     // [2][BBUF]

    int tid = threadIdx.x;
    int lane = tid & 31, wid = tid >> 5;
    int wm = (wid >> 2) * 64;      // warp M offset (0/64)
    int wn = (wid & 3) * 32;       // warp N offset (0/32/64/96)

    float acc[4][4][4];
#pragma unroll
    for (int mi = 0; mi < 4; mi++)
#pragma unroll
        for (int ni = 0; ni < 4; ni++)
#pragma unroll
            for (int c = 0; c < 4; c++) acc[mi][ni][c] = 0.f;

    float4 aReg[4], bReg[4];

    // ---- prologue: load tile 0 ----
#pragma unroll
    for (int l = 0; l < 4; l++) {
        int idx = tid + l * 256;
        int row = idx >> 3, cv = (idx & 7) << 2;           // A: 128x32
        aReg[l] = *(const float4*)(A + (size_t)(bm + row) * K + cv);
        int kr = idx >> 5, nc = (idx & 31) << 2;           // B: 32x128
        bReg[l] = *(const float4*)(B + (size_t)kr * N + bn + nc);
    }
#pragma unroll
    for (int l = 0; l < 4; l++) {
        int idx = tid + l * 256;
        int row = idx >> 3, cv = (idx & 7) << 2;
        uint32_t* d = (uint32_t*)&As[row * ASTR + cv];
        d[0] = f2tf32(aReg[l].x); d[1] = f2tf32(aReg[l].y);
        d[2] = f2tf32(aReg[l].z); d[3] = f2tf32(aReg[l].w);
        int kr = idx >> 5, nc = (idx & 31) << 2;
        uint32_t* e = (uint32_t*)&Bs[kr * BSTR + nc];
        e[0] = f2tf32(bReg[l].x); e[1] = f2tf32(bReg[l].y);
        e[2] = f2tf32(bReg[l].z); e[3] = f2tf32(bReg[l].w);
    }
    __syncthreads();

    int niter = K / BK;
    for (int i = 0; i < niter; i++) {
        int cur = i & 1, nxt = cur ^ 1;
        // issue next tile's LDG early
        if (i + 1 < niter) {
            int k0 = (i + 1) * BK;
#pragma unroll
            for (int l = 0; l < 4; l++) {
                int idx = tid + l * 256;
                int row = idx >> 3, cv = (idx & 7) << 2;
                aReg[l] = *(const float4*)(A + (size_t)(bm + row) * K + k0 + cv);
                int kr = idx >> 5, nc = (idx & 31) << 2;
                bReg[l] = *(const float4*)(B + (size_t)(k0 + kr) * N + bn + nc);
            }
        }

        // ---- compute on buffer cur ----
        const float* Ab = As + cur * ABUF;
        const float* Bb = Bs + cur * BBUF;
#pragma unroll
        for (int k = 0; k < 4; k++) {
            uint32_t af[4][4], bf[4][2];
            int r0 = wm + (lane >> 2);
            int c0 = k * 8 + (lane & 3);
#pragma unroll
            for (int mi = 0; mi < 4; mi++) {
                const float* p = Ab + (r0 + mi * 16) * ASTR;
                af[mi][0] = __float_as_uint(p[c0]);
                af[mi][1] = __float_as_uint(p[8 * ASTR + c0]);
                af[mi][2] = __float_as_uint(p[c0 + 4]);
                af[mi][3] = __float_as_uint(p[8 * ASTR + c0 + 4]);
            }
            int kr = k * 8 + (lane & 3);
            int nc = wn + (lane >> 2);
#pragma unroll
            for (int ni = 0; ni < 4; ni++) {
                bf[ni][0] = __float_as_uint(Bb[kr * BSTR + nc + ni * 8]);
                bf[ni][1] = __float_as_uint(Bb[(kr + 4) * BSTR + nc + ni * 8]);
            }
#pragma unroll
            for (int mi = 0; mi < 4; mi++)
#pragma unroll
                for (int ni = 0; ni < 4; ni++)
                    mma_tf32(acc[mi][ni], af[mi], bf[ni]);
        }

        // stage next tile (into buffer consumed two iters ago)
        if (i + 1 < niter) {
            float* An = As + nxt * ABUF;
            float* Bn = Bs + nxt * BBUF;
#pragma unroll
            for (int l = 0; l < 4; l++) {
                int idx = tid + l * 256;
                int row = idx >> 3, cv = (idx & 7) << 2;
                uint32_t* d = (uint32_t*)&An[row * ASTR + cv];
                d[0] = f2tf32(aReg[l].x); d[1] = f2tf32(aReg[l].y);
                d[2] = f2tf32(aReg[l].z); d[3] = f2tf32(aReg[l].w);
                int kr = idx >> 5, nc = (idx & 31) << 2;
                uint32_t* e = (uint32_t*)&Bn[kr * BSTR + nc];
                e[0] = f2tf32(bReg[l].x); e[1] = f2tf32(bReg[l].y);
                e[2] = f2tf32(bReg[l].z); e[3] = f2tf32(bReg[l].w);
            }
        }
        __syncthreads();
    }

    // ---- epilogue ----
    int r = bm + wm + (lane >> 2);
    int c = bn + wn + (lane & 3) * 2;
#pragma unroll
    for (int mi = 0; mi < 4; mi++) {
#pragma unroll
        for (int ni = 0; ni < 4; ni++) {
            float2 w0 = make_float2(acc[mi][ni][0], acc[mi][ni][1]);
            float2 w1 = make_float2(acc[mi][ni][2], acc[mi][ni][3]);
            *(float2*)(C + (size_t)(r + mi * 16)     * N + c + ni * 8) = w0;
            *(float2*)(C + (size_t)(r + mi * 16 + 8) * N + c + ni * 8) = w1;
        }
    }
}

// Fused QKV projection: grid.x = 16 (Wq) + 4 (Wk) + 4 (Wv) column blocks.
__global__ __launch_bounds__(256) void qkv_mma(const float* __restrict__ x,
                                               const float* __restrict__ Wq,
                                               const float* __restrict__ Wk,
                                               const float* __restrict__ Wv,
                                               float* __restrict__ q,
                                               float* __restrict__ k,
                                               float* __restrict__ v)
{
    int bx = blockIdx.x, bm = blockIdx.y << 7;
    const float* B; float* C; int N, bn;
    if (bx < 16)      { B = Wq; C = q; N = DIM;   bn = bx << 7; }
    else if (bx < 20) { B = Wk; C = k; N = KVDIM; bn = (bx - 16) << 7; }
    else              { B = Wv; C = v; N = KVDIM; bn = (bx - 20) << 7; }
    gemm_core(x, B, C, N, DIM, bm, bn);
}

__global__ __launch_bounds__(256) void gemm_mma(const float* __restrict__ A,
                                                const float* __restrict__ B,
                                                float* __restrict__ C,
                                                int N, int K)
{
    gemm_core(A, B, C, N, K, blockIdx.y << 7, blockIdx.x << 7);
}

// ---------------------------------------------------------------------------
// RoPE (in-place)
// ---------------------------------------------------------------------------
__global__ void rope_k(float* __restrict__ d, const float* __restrict__ c,
                       const float* __restrict__ s, int nheads)
{
    int idx = blockIdx.x * blockDim.x + threadIdx.x;
    int total = MS * nheads * (HD / 2);
    if (idx >= total) return;
    int p  = idx & 63;
    int h  = (idx >> 6) % nheads;
    int bs = idx / (64 * nheads);
    int sq = bs & (SEQ - 1);
    float cv = c[sq * 64 + p];
    float sv = s[sq * 64 + p];
    float* base = d + (size_t)bs * nheads * HD + h * HD + 2 * p;
    float xr = base[0], xi = base[1];
    base[0] = xr * cv - xi * sv;
    base[1] = xr * sv + xi * cv;
}

// ---------------------------------------------------------------------------
// Flash attention (causal, GQA) — fp32
// ---------------------------------------------------------------------------
__global__ __launch_bounds__(256) void attn_k(const float* __restrict__ Q,
                                              const float* __restrict__ Kg,
                                              const float* __restrict__ Vg,
                                              float* __restrict__ O)
{
    extern __shared__ float smf[];
    float* Qs   = smf;                // [64][132]
    float* Kst  = Qs  + 64 * 132;     // [128][65]
    float* Vs   = Kst + 128 * 65;     // [64][132]
    float* Sc   = Vs  + 64 * 132;     // [64][68]
    float* lrow = Sc  + 64 * 68;      // [64]
    float* crow = lrow + 64;          // [64]

    int tid = threadIdx.x;
    int tx = tid & 15, ty = tid >> 4;
    int mblk = blockIdx.x;
    int bh = blockIdx.y;
    int b = bh >> 4, h = bh & 15;
    int g = h >> 2;
    int m0 = mblk * 64;
    const float scale = 0.08838834764831845f;

    const float* qbase = Q + ((size_t)(b * SEQ + m0)) * DIM + h * HD;
#pragma unroll
    for (int l = 0; l < 8; l++) {
        int i4 = tid + l * 256;
        int row = i4 >> 5;
        int dc  = (i4 & 31) << 2;
        *(float4*)&Qs[row * 132 + dc] =
            *(const float4*)(qbase + (size_t)row * DIM + dc);
    }

    float oacc[4][8];
#pragma unroll
    for (int i = 0; i < 4; i++)
#pragma unroll
        for (int c = 0; c < 8; c++) oacc[i][c] = 0.f;

    float mreg = -1e30f, lreg = 0.f;

    const float* kbase = Kg + (size_t)(b * SEQ) * KVDIM + g * HD;
    const float* vbase = Vg + (size_t)(b * SEQ) * KVDIM + g * HD;

    for (int n0 = 0; n0 <= m0; n0 += 64) {
        __syncthreads();
#pragma unroll
        for (int l = 0; l < 8; l++) {
            int i4 = tid + l * 256;
            int row = i4 >> 5;
            int dc  = (i4 & 31) << 2;
            float4 kv = *(const float4*)(kbase + (size_t)(n0 + row) * KVDIM + dc);
            Kst[(dc + 0) * 65 + row] = kv.x;
            Kst[(dc + 1) * 65 + row] = kv.y;
            Kst[(dc + 2) * 65 + row] = kv.z;
            Kst[(dc + 3) * 65 + row] = kv.w;
            *(float4*)&Vs[row * 132 + dc] =
                *(const float4*)(vbase + (size_t)(n0 + row) * KVDIM + dc);
        }
        __syncthreads();

        float sacc[4][4];
#pragma unroll
        for (int i = 0; i < 4; i++)
#pragma unroll
            for (int j = 0; j < 4; j++) sacc[i][j] = 0.f;

        for (int d = 0; d < HD; d++) {
            float a[4], kq[4];
#pragma unroll
            for (int i = 0; i < 4; i++) a[i]  = Qs[(ty * 4 + i) * 132 + d];
#pragma unroll
            for (int j = 0; j < 4; j++) kq[j] = Kst[d * 65 + tx * 4 + j];
#pragma unroll
            for (int i = 0; i < 4; i++)
#pragma unroll
                for (int j = 0; j < 4; j++) sacc[i][j] += a[i] * kq[j];
        }

#pragma unroll
        for (int i = 0; i < 4; i++) {
            int qi = m0 + ty * 4 + i;
#pragma unroll
            for (int j = 0; j < 4; j++) {
                int kj = n0 + tx * 4 + j;
                float v = (kj <= qi) ? sacc[i][j] * scale : -1e30f;
                Sc[(ty * 4 + i) * 68 + tx * 4 + j] = v;
            }
        }
        __syncthreads();

        if (tid < 64) {
            float rm = -1e30f;
            for (int j = 0; j < 64; j++) rm = fmaxf(rm, Sc[tid * 68 + j]);
            float nm = fmaxf(mreg, rm);
            float cf = __expf(mreg - nm);
            float sum = 0.f;
            for (int j = 0; j < 64; j++) {
                float p = __expf(Sc[tid * 68 + j] - nm);
                Sc[tid * 68 + j] = p;
                sum += p;
            }
            lreg = lreg * cf + sum;
            mreg = nm;
            crow[tid] = cf;
            lrow[tid] = lreg;
        }
        __syncthreads();

#pragma unroll
        for (int i = 0; i < 4; i++) {
            float cf = crow[ty * 4 + i];
#pragma unroll
            for (int c = 0; c < 8; c++) oacc[i][c] *= cf;
        }
        for (int j = 0; j < 64; j++) {
            float p[4];
#pragma unroll
            for (int i = 0; i < 4; i++) p[i] = Sc[(ty * 4 + i) * 68 + j];
            float4 v0 = *(float4*)&Vs[j * 132 + tx * 4];
            float4 v1 = *(float4*)&Vs[j * 132 + 64 + tx * 4];
            float vv[8] = {v0.x, v0.y, v0.z, v0.w, v1.x, v1.y, v1.z, v1.w};
#pragma unroll
            for (int i = 0; i < 4; i++)
#pragma unroll
                for (int c = 0; c < 8; c++) oacc[i][c] += p[i] * vv[c];
        }
    }

#pragma unroll
    for (int i = 0; i < 4; i++) {
        float inv = 1.f / lrow[ty * 4 + i];
        int qi = m0 + ty * 4 + i;
        float* obase = O + ((size_t)(b * SEQ + qi)) * DIM + h * HD;
        float4 w0 = make_float4(oacc[i][0] * inv, oacc[i][1] * inv,
                                oacc[i][2] * inv, oacc[i][3] * inv);
        float4 w1 = make_float4(oacc[i][4] * inv, oacc[i][5] * inv,
                                oacc[i][6] * inv, oacc[i][7] * inv);
        *(float4*)(obase + tx * 4) = w0;
        *(float4*)(obase + 64 + tx * 4) = w1;
    }
}

// ---------------------------------------------------------------------------
extern "C" void kernel_launch(void* const* d_in, const int* in_sizes, int n_in,
                              void* d_out, int out_size)
{
    const float* x  = (const float*)d_in[0];
    const float* fc = (const float*)d_in[1];
    const float* fs = (const float*)d_in[2];
    const float* Wq = (const float*)d_in[3];
    const float* Wk = (const float*)d_in[4];
    const float* Wv = (const float*)d_in[5];
    const float* Wo = (const float*)d_in[6];
    float* out = (float*)d_out;

    float *q, *k, *v, *att;
    cudaGetSymbolAddress((void**)&q,   g_q);
    cudaGetSymbolAddress((void**)&k,   g_k);
    cudaGetSymbolAddress((void**)&v,   g_v);
    cudaGetSymbolAddress((void**)&att, g_att);

    int asmem = (64 * 132 + 128 * 65 + 64 * 132 + 64 * 68 + 128) * sizeof(float);
    cudaFuncSetAttribute(qkv_mma,  cudaFuncAttributeMaxDynamicSharedMemorySize, GSMEM);
    cudaFuncSetAttribute(gemm_mma, cudaFuncAttributeMaxDynamicSharedMemorySize, GSMEM);
    cudaFuncSetAttribute(attn_k,   cudaFuncAttributeMaxDynamicSharedMemorySize, asmem);

    // Fused QKV projections (tf32 mma)
    qkv_mma<<<dim3(24, MS / 128), 256, GSMEM>>>(x, Wq, Wk, Wv, q, k, v);

    // RoPE
    rope_k<<<(MS * NH  * 64 + 255) / 256, 256>>>(q, fc, fs, NH);
    rope_k<<<(MS * NKV * 64 + 255) / 256, 256>>>(k, fc, fs, NKV);

    // Attention (fp32)
    attn_k<<<dim3(SEQ / 64, BATCH * NH), 256, asmem>>>(q, k, v, att);

    // Output projection (tf32 mma)
    gemm_mma<<<dim3(DIM / 128, MS / 128), 256, GSMEM>>>(att, Wo, out, DIM, DIM);
}

// round 8
// speedup vs baseline: 4.0963x; 2.4343x over previous
#include <cuda_runtime.h>
#include <cuda_fp16.h>
#include <cstdint>

#define BATCH 2
#define SEQ   2048
#define DIM   2048
#define NH    16
#define NKV   4
#define HD    128
#define KVDIM (NKV*HD)      // 512
#define MS    (BATCH*SEQ)   // 4096

// Scratch (device globals — no allocation allowed)
__device__ float g_q[MS * DIM];
__device__ float g_k[MS * KVDIM];
__device__ float g_v[MS * KVDIM];
__device__ float g_att[MS * DIM];

// ===========================================================================
// mma / ldmatrix primitives (fp16 inputs, fp32 accum; base-ISA sm_80+)
// ===========================================================================
__device__ __forceinline__ uint32_t smem_u32(const void* p) {
    uint32_t a;
    asm("{ .reg .u64 t; cvta.to.shared.u64 t, %1; cvt.u32.u64 %0, t; }"
        : "=r"(a) : "l"(p));
    return a;
}
__device__ __forceinline__ void ldmx4(uint32_t* r, uint32_t addr) {
    asm volatile("ldmatrix.sync.aligned.m8n8.x4.shared.b16 {%0,%1,%2,%3}, [%4];"
                 : "=r"(r[0]), "=r"(r[1]), "=r"(r[2]), "=r"(r[3]) : "r"(addr));
}
__device__ __forceinline__ void ldmx4t(uint32_t* r, uint32_t addr) {
    asm volatile("ldmatrix.sync.aligned.m8n8.x4.trans.shared.b16 {%0,%1,%2,%3}, [%4];"
                 : "=r"(r[0]), "=r"(r[1]), "=r"(r[2]), "=r"(r[3]) : "r"(addr));
}
__device__ __forceinline__ void mma_f16(float* c, const uint32_t* a,
                                        const uint32_t* b) {
    asm volatile(
        "mma.sync.aligned.m16n8k16.row.col.f32.f16.f16.f32 "
        "{%0,%1,%2,%3}, {%4,%5,%6,%7}, {%8,%9}, {%0,%1,%2,%3};"
        : "+f"(c[0]), "+f"(c[1]), "+f"(c[2]), "+f"(c[3])
        : "r"(a[0]), "r"(a[1]), "r"(a[2]), "r"(a[3]), "r"(b[0]), "r"(b[1]));
}

// ===========================================================================
// fp16 GEMM: C[M,N] = A[M,K] @ B[K,N], row-major fp32 in/out.
// CTA 128x128, BK=32, 256 thr, warps 2(M)x4(N), warp tile 64x32.
// A smem [128][40]h (80B stride: ldmatrix conflict-free), B smem [32][136]h.
// ===========================================================================
#define ASTRH 40
#define BSTRH 136
#define ABUFB (128*ASTRH*2)     // 10240 B
#define BBUFB (32*BSTRH*2)      // 8704 B
#define GSMEM (2*ABUFB + 2*BBUFB)   // 37888 B

__device__ __forceinline__ void gemm_core(const float* __restrict__ A,
                                          const float* __restrict__ B,
                                          float* __restrict__ C,
                                          int N, int K, int bm, int bn)
{
    extern __shared__ char smem[];
    half* As = (half*)smem;                       // [2][128][40]
    half* Bs = (half*)(smem + 2 * ABUFB);         // [2][32][136]
    uint32_t sb = smem_u32(smem);

    int tid = threadIdx.x;
    int lane = tid & 31, wid = tid >> 5;
    int wm = (wid >> 2) * 64;
    int wn = (wid & 3) * 32;

    float acc[4][4][4];
#pragma unroll
    for (int mi = 0; mi < 4; mi++)
#pragma unroll
        for (int ni = 0; ni < 4; ni++)
#pragma unroll
            for (int c = 0; c < 4; c++) acc[mi][ni][c] = 0.f;

    float4 aReg[4], bReg[4];

    // ---- prologue ----
#pragma unroll
    for (int l = 0; l < 4; l++) {
        int idx = tid + l * 256;
        int row = idx >> 3, kc = (idx & 7) << 2;
        aReg[l] = *(const float4*)(A + (size_t)(bm + row) * K + kc);
        int kr = idx >> 5, nc = (idx & 31) << 2;
        bReg[l] = *(const float4*)(B + (size_t)kr * N + bn + nc);
    }
#pragma unroll
    for (int l = 0; l < 4; l++) {
        int idx = tid + l * 256;
        int row = idx >> 3, kc = (idx & 7) << 2;
        half2* d = (half2*)(As + row * ASTRH + kc);
        d[0] = __floats2half2_rn(aReg[l].x, aReg[l].y);
        d[1] = __floats2half2_rn(aReg[l].z, aReg[l].w);
        int kr = idx >> 5, nc = (idx & 31) << 2;
        half2* e = (half2*)(Bs + kr * BSTRH + nc);
        e[0] = __floats2half2_rn(bReg[l].x, bReg[l].y);
        e[1] = __floats2half2_rn(bReg[l].z, bReg[l].w);
    }
    __syncthreads();

    int niter = K >> 5;
    for (int i = 0; i < niter; i++) {
        int cur = i & 1, nxt = cur ^ 1;
        if (i + 1 < niter) {
            int k0 = (i + 1) << 5;
#pragma unroll
            for (int l = 0; l < 4; l++) {
                int idx = tid + l * 256;
                int row = idx >> 3, kc = (idx & 7) << 2;
                aReg[l] = *(const float4*)(A + (size_t)(bm + row) * K + k0 + kc);
                int kr = idx >> 5, nc = (idx & 31) << 2;
                bReg[l] = *(const float4*)(B + (size_t)(k0 + kr) * N + bn + nc);
            }
        }

        uint32_t ab = sb + cur * ABUFB;
        uint32_t bb = sb + 2 * ABUFB + cur * BBUFB;
#pragma unroll
        for (int ks = 0; ks < 2; ks++) {
            uint32_t af[4][4], bf[2][4];
#pragma unroll
            for (int mi = 0; mi < 4; mi++)
                ldmx4(af[mi], ab + (wm + mi * 16 + (lane & 15)) * 80
                               + ks * 32 + ((lane >> 4) << 4));
#pragma unroll
            for (int nh = 0; nh < 2; nh++)
                ldmx4t(bf[nh], bb + (ks * 16 + (lane & 7) + ((lane >> 3) & 1) * 8) * 272
                                + (wn + nh * 16 + ((lane >> 4) << 3)) * 2);
#pragma unroll
            for (int mi = 0; mi < 4; mi++)
#pragma unroll
                for (int ni = 0; ni < 4; ni++)
                    mma_f16(acc[mi][ni], af[mi], &bf[ni >> 1][(ni & 1) * 2]);
        }

        if (i + 1 < niter) {
            half* An = As + nxt * (ABUFB / 2);
            half* Bn = Bs + nxt * (BBUFB / 2);
#pragma unroll
            for (int l = 0; l < 4; l++) {
                int idx = tid + l * 256;
                int row = idx >> 3, kc = (idx & 7) << 2;
                half2* d = (half2*)(An + row * ASTRH + kc);
                d[0] = __floats2half2_rn(aReg[l].x, aReg[l].y);
                d[1] = __floats2half2_rn(aReg[l].z, aReg[l].w);
                int kr = idx >> 5, nc = (idx & 31) << 2;
                half2* e = (half2*)(Bn + kr * BSTRH + nc);
                e[0] = __floats2half2_rn(bReg[l].x, bReg[l].y);
                e[1] = __floats2half2_rn(bReg[l].z, bReg[l].w);
            }
        }
        __syncthreads();
    }

    // ---- epilogue ----
    int r = bm + wm + (lane >> 2);
    int c = bn + wn + (lane & 3) * 2;
#pragma unroll
    for (int mi = 0; mi < 4; mi++) {
#pragma unroll
        for (int ni = 0; ni < 4; ni++) {
            *(float2*)(C + (size_t)(r + mi * 16)     * N + c + ni * 8) =
                make_float2(acc[mi][ni][0], acc[mi][ni][1]);
            *(float2*)(C + (size_t)(r + mi * 16 + 8) * N + c + ni * 8) =
                make_float2(acc[mi][ni][2], acc[mi][ni][3]);
        }
    }
}

// Fused QKV projection: grid.x = 16 (Wq) + 4 (Wk) + 4 (Wv) column blocks.
__global__ __launch_bounds__(256) void qkv_mma(const float* __restrict__ x,
                                               const float* __restrict__ Wq,
                                               const float* __restrict__ Wk,
                                               const float* __restrict__ Wv,
                                               float* __restrict__ q,
                                               float* __restrict__ k,
                                               float* __restrict__ v)
{
    int bx = blockIdx.x, bm = blockIdx.y << 7;
    const float* B; float* C; int N, bn;
    if (bx < 16)      { B = Wq; C = q; N = DIM;   bn = bx << 7; }
    else if (bx < 20) { B = Wk; C = k; N = KVDIM; bn = (bx - 16) << 7; }
    else              { B = Wv; C = v; N = KVDIM; bn = (bx - 20) << 7; }
    gemm_core(x, B, C, N, DIM, bm, bn);
}

__global__ __launch_bounds__(256) void gemm_mma(const float* __restrict__ A,
                                                const float* __restrict__ B,
                                                float* __restrict__ C,
                                                int N, int K)
{
    gemm_core(A, B, C, N, K, blockIdx.y << 7, blockIdx.x << 7);
}

// ---------------------------------------------------------------------------
// RoPE (in-place)
// ---------------------------------------------------------------------------
__global__ void rope_k(float* __restrict__ d, const float* __restrict__ c,
                       const float* __restrict__ s, int nheads)
{
    int idx = blockIdx.x * blockDim.x + threadIdx.x;
    int total = MS * nheads * (HD / 2);
    if (idx >= total) return;
    int p  = idx & 63;
    int h  = (idx >> 6) % nheads;
    int bs = idx / (64 * nheads);
    int sq = bs & (SEQ - 1);
    float cv = c[sq * 64 + p];
    float sv = s[sq * 64 + p];
    float* base = d + (size_t)bs * nheads * HD + h * HD + 2 * p;
    float xr = base[0], xi = base[1];
    base[0] = xr * cv - xi * sv;
    base[1] = xr * sv + xi * cv;
}

// ===========================================================================
// Flash attention, fp16 mma. CTA = 64 q-rows x one (b,h). 256 thr, 8 warps:
// QK warps 4(M)x2(N) (16x32 tiles); PV warps 4(M)x2(N) (16x64 tiles).
// Q prescaled by 1/sqrt(d) at staging. K b-frags: plain ldmatrix on K-major
// K tile; V b-frags: ldmatrix.trans on row-major V tile (no transpose stage).
// ===========================================================================
#define QKV_STR 136     // halfs (272 B: conflict-free ldmatrix)
#define SC_STR  68      // floats
#define PH_STR  72      // halfs (144 B: conflict-free ldmatrix)
#define Q_OFF   0
#define K_OFF   17408
#define V_OFF   34816
#define SC_OFF  52224
#define PH_OFF  69632
#define LR_OFF  78848
#define CR_OFF  79104
#define ATT_SMEM 79360

__global__ __launch_bounds__(256) void attn_mma(const float* __restrict__ Q,
                                                const float* __restrict__ Kg,
                                                const float* __restrict__ Vg,
                                                float* __restrict__ O)
{
    extern __shared__ char smem[];
    half*  Qs = (half*)(smem + Q_OFF);
    half*  Ks = (half*)(smem + K_OFF);
    half*  Vs = (half*)(smem + V_OFF);
    float* Sc = (float*)(smem + SC_OFF);
    half*  Ph = (half*)(smem + PH_OFF);
    float* lrow = (float*)(smem + LR_OFF);
    float* crow = (float*)(smem + CR_OFF);
    uint32_t sbu = smem_u32(smem);

    int tid = threadIdx.x;
    int lane = tid & 31, wid = tid >> 5;
    int wm  = (wid >> 1) * 16;     // 0/16/32/48
    int wn  = (wid & 1) * 32;      // QK: 0/32
    int wnv = (wid & 1) * 64;      // PV: 0/64
    int mblk = blockIdx.x;
    int bh = blockIdx.y;
    int b = bh >> 4, h = bh & 15;
    int g = h >> 2;
    int m0 = mblk * 64;
    const float scale = 0.08838834764831845f;  // 1/sqrt(128)

    // ---- stage Q (prescaled) ----
    const float* qbase = Q + ((size_t)(b * SEQ + m0)) * DIM + h * HD;
#pragma unroll
    for (int l = 0; l < 8; l++) {
        int i4 = tid + l * 256;
        int row = i4 >> 5, dc = (i4 & 31) << 2;
        float4 v = *(const float4*)(qbase + (size_t)row * DIM + dc);
        half2* d = (half2*)(Qs + row * QKV_STR + dc);
        d[0] = __floats2half2_rn(v.x * scale, v.y * scale);
        d[1] = __floats2half2_rn(v.z * scale, v.w * scale);
    }

    float oacc[8][4];
#pragma unroll
    for (int t = 0; t < 8; t++)
#pragma unroll
        for (int c = 0; c < 4; c++) oacc[t][c] = 0.f;

    float mreg = -1e30f, lreg = 0.f;   // per-row state, thread tid<64 owns row tid

    const float* kbase = Kg + (size_t)(b * SEQ) * KVDIM + g * HD;
    const float* vbase = Vg + (size_t)(b * SEQ) * KVDIM + g * HD;

    for (int n0 = 0; n0 <= m0; n0 += 64) {
        __syncthreads();   // prior iteration's consumers done
        // ---- stage K, V (row-major fp16) ----
#pragma unroll
        for (int l = 0; l < 8; l++) {
            int i4 = tid + l * 256;
            int row = i4 >> 5, dc = (i4 & 31) << 2;
            const float* src = kbase + (size_t)(n0 + row) * KVDIM + dc;
            float4 kv = *(const float4*)src;
            half2* d = (half2*)(Ks + row * QKV_STR + dc);
            d[0] = __floats2half2_rn(kv.x, kv.y);
            d[1] = __floats2half2_rn(kv.z, kv.w);
            float4 vv = *(const float4*)(vbase + (size_t)(n0 + row) * KVDIM + dc);
            half2* e = (half2*)(Vs + row * QKV_STR + dc);
            e[0] = __floats2half2_rn(vv.x, vv.y);
            e[1] = __floats2half2_rn(vv.z, vv.w);
        }
        __syncthreads();

        // ---- S = Q K^T  (fp16 mma, k over HD=128 -> 8 steps) ----
        float sacc[4][4];
#pragma unroll
        for (int ni = 0; ni < 4; ni++)
#pragma unroll
            for (int c = 0; c < 4; c++) sacc[ni][c] = 0.f;

#pragma unroll
        for (int ks = 0; ks < 8; ks++) {
            uint32_t af[4], bf[2][4];
            ldmx4(af, sbu + Q_OFF + (wm + (lane & 15)) * 272
                       + ks * 32 + ((lane >> 4) << 4));
#pragma unroll
            for (int nh = 0; nh < 2; nh++)
                ldmx4(bf[nh], sbu + K_OFF
                       + (wn + nh * 16 + ((lane >> 4) << 3) + (lane & 7)) * 272
                       + ks * 32 + (((lane >> 3) & 1) << 4));
#pragma unroll
            for (int ni = 0; ni < 4; ni++)
                mma_f16(sacc[ni], af, &bf[ni >> 1][(ni & 1) * 2]);
        }

        // ---- mask + stage S (fp32) ----
        {
            int r0 = wm + (lane >> 2);
            int qi0 = m0 + r0, qi1 = qi0 + 8;
#pragma unroll
            for (int ni = 0; ni < 4; ni++) {
                int cb = wn + ni * 8 + 2 * (lane & 3);
                int kj = n0 + cb;
                Sc[r0 * SC_STR + cb]           = (kj     <= qi0) ? sacc[ni][0] : -1e30f;
                Sc[r0 * SC_STR + cb + 1]       = (kj + 1 <= qi0) ? sacc[ni][1] : -1e30f;
                Sc[(r0 + 8) * SC_STR + cb]     = (kj     <= qi1) ? sacc[ni][2] : -1e30f;
                Sc[(r0 + 8) * SC_STR + cb + 1] = (kj + 1 <= qi1) ? sacc[ni][3] : -1e30f;
            }
        }
        __syncthreads();

        // ---- online softmax (thread tid<64 owns row tid); P -> fp16 ----
        if (tid < 64) {
            const float* srow = Sc + tid * SC_STR;
            half2* prow = (half2*)(Ph + tid * PH_STR);
            float rm = -1e30f;
#pragma unroll 8
            for (int j = 0; j < 64; j++) rm = fmaxf(rm, srow[j]);
            float nm = fmaxf(mreg, rm);
            float cf = __expf(mreg - nm);
            float sum = 0.f;
#pragma unroll 4
            for (int j = 0; j < 64; j += 2) {
                float p0 = __expf(srow[j] - nm);
                float p1 = __expf(srow[j + 1] - nm);
                prow[j >> 1] = __floats2half2_rn(p0, p1);
                sum += p0 + p1;
            }
            lreg = lreg * cf + sum;
            mreg = nm;
            crow[tid] = cf;
            lrow[tid] = lreg;
        }
        __syncthreads();

        // ---- rescale O, then O += P V ----
        {
            float cf0 = crow[wm + (lane >> 2)];
            float cf1 = crow[wm + 8 + (lane >> 2)];
#pragma unroll
            for (int t = 0; t < 8; t++) {
                oacc[t][0] *= cf0; oacc[t][1] *= cf0;
                oacc[t][2] *= cf1; oacc[t][3] *= cf1;
            }
        }
#pragma unroll
        for (int ks = 0; ks < 4; ks++) {
            uint32_t af[4], bv[4][4];
            ldmx4(af, sbu + PH_OFF + (wm + (lane & 15)) * 144
                       + ks * 32 + ((lane >> 4) << 4));
#pragma unroll
            for (int nh = 0; nh < 4; nh++)
                ldmx4t(bv[nh], sbu + V_OFF
                        + (ks * 16 + (lane & 7) + ((lane >> 3) & 1) * 8) * 272
                        + (wnv + nh * 16 + ((lane >> 4) << 3)) * 2);
#pragma unroll
            for (int ni = 0; ni < 8; ni++)
                mma_f16(oacc[ni], af, &bv[ni >> 1][(ni & 1) * 2]);
        }
    }

    // ---- finalize ----
    {
        float inv0 = 1.f / lrow[wm + (lane >> 2)];
        float inv1 = 1.f / lrow[wm + 8 + (lane >> 2)];
        int r0 = m0 + wm + (lane >> 2);
        float* ob0 = O + ((size_t)(b * SEQ + r0))     * DIM + h * HD;
        float* ob1 = O + ((size_t)(b * SEQ + r0 + 8)) * DIM + h * HD;
#pragma unroll
        for (int ni = 0; ni < 8; ni++) {
            int cb = wnv + ni * 8 + 2 * (lane & 3);
            *(float2*)(ob0 + cb) = make_float2(oacc[ni][0] * inv0,
                                               oacc[ni][1] * inv0);
            *(float2*)(ob1 + cb) = make_float2(oacc[ni][2] * inv1,
                                               oacc[ni][3] * inv1);
        }
    }
}

// ---------------------------------------------------------------------------
extern "C" void kernel_launch(void* const* d_in, const int* in_sizes, int n_in,
                              void* d_out, int out_size)
{
    const float* x  = (const float*)d_in[0];
    const float* fc = (const float*)d_in[1];
    const float* fs = (const float*)d_in[2];
    const float* Wq = (const float*)d_in[3];
    const float* Wk = (const float*)d_in[4];
    const float* Wv = (const float*)d_in[5];
    const float* Wo = (const float*)d_in[6];
    float* out = (float*)d_out;

    float *q, *k, *v, *att;
    cudaGetSymbolAddress((void**)&q,   g_q);
    cudaGetSymbolAddress((void**)&k,   g_k);
    cudaGetSymbolAddress((void**)&v,   g_v);
    cudaGetSymbolAddress((void**)&att, g_att);

    cudaFuncSetAttribute(qkv_mma,  cudaFuncAttributeMaxDynamicSharedMemorySize, GSMEM);
    cudaFuncSetAttribute(gemm_mma, cudaFuncAttributeMaxDynamicSharedMemorySize, GSMEM);
    cudaFuncSetAttribute(attn_mma, cudaFuncAttributeMaxDynamicSharedMemorySize, ATT_SMEM);

    // Fused QKV projections (fp16 mma)
    qkv_mma<<<dim3(24, MS / 128), 256, GSMEM>>>(x, Wq, Wk, Wv, q, k, v);

    // RoPE
    rope_k<<<(MS * NH  * 64 + 255) / 256, 256>>>(q, fc, fs, NH);
    rope_k<<<(MS * NKV * 64 + 255) / 256, 256>>>(k, fc, fs, NKV);

    // Attention (fp16 mma flash)
    attn_mma<<<dim3(SEQ / 64, BATCH * NH), 256, ATT_SMEM>>>(q, k, v, att);

    // Output projection (fp16 mma)
    gemm_mma<<<dim3(DIM / 128, MS / 128), 256, GSMEM>>>(att, Wo, out, DIM, DIM);
}

// round 10
// speedup vs baseline: 7.0252x; 1.7150x over previous
#include <cuda_runtime.h>
#include <cuda_fp16.h>
#include <cstdint>

#define BATCH 2
#define SEQ   2048
#define DIM   2048
#define NH    16
#define NKV   4
#define HD    128
#define KVDIM (NKV*HD)      // 512
#define MS    (BATCH*SEQ)   // 4096

// ---- scratch (device globals; no allocation allowed) ----
__device__ float g_q[MS * DIM];
__device__ float g_k[MS * KVDIM];
__device__ float g_v[MS * KVDIM];
__device__ half  g_xh [MS * DIM];
__device__ half  g_wqh[DIM * DIM];
__device__ half  g_wkh[DIM * KVDIM];
__device__ half  g_wvh[DIM * KVDIM];
__device__ half  g_woh[DIM * DIM];
__device__ half  g_qh [MS * DIM];
__device__ half  g_kh [MS * KVDIM];
__device__ half  g_vh [MS * KVDIM];
__device__ half  g_atth[MS * DIM];

// ===========================================================================
// primitives
// ===========================================================================
__device__ __forceinline__ uint32_t smem_u32(const void* p) {
    uint32_t a;
    asm("{ .reg .u64 t; cvta.to.shared.u64 t, %1; cvt.u32.u64 %0, t; }"
        : "=r"(a) : "l"(p));
    return a;
}
__device__ __forceinline__ void ldmx4(uint32_t* r, uint32_t addr) {
    asm volatile("ldmatrix.sync.aligned.m8n8.x4.shared.b16 {%0,%1,%2,%3}, [%4];"
                 : "=r"(r[0]), "=r"(r[1]), "=r"(r[2]), "=r"(r[3]) : "r"(addr));
}
__device__ __forceinline__ void ldmx4t(uint32_t* r, uint32_t addr) {
    asm volatile("ldmatrix.sync.aligned.m8n8.x4.trans.shared.b16 {%0,%1,%2,%3}, [%4];"
                 : "=r"(r[0]), "=r"(r[1]), "=r"(r[2]), "=r"(r[3]) : "r"(addr));
}
__device__ __forceinline__ void mma_f16(float* c, const uint32_t* a,
                                        const uint32_t* b) {
    asm volatile(
        "mma.sync.aligned.m16n8k16.row.col.f32.f16.f16.f32 "
        "{%0,%1,%2,%3}, {%4,%5,%6,%7}, {%8,%9}, {%0,%1,%2,%3};"
        : "+f"(c[0]), "+f"(c[1]), "+f"(c[2]), "+f"(c[3])
        : "r"(a[0]), "r"(a[1]), "r"(a[2]), "r"(a[3]), "r"(b[0]), "r"(b[1]));
}
__device__ __forceinline__ void cpasync16(uint32_t dst, const void* src) {
    asm volatile("cp.async.cg.shared.global [%0], [%1], 16;"
                 :: "r"(dst), "l"(src));
}
#define CP_COMMIT() asm volatile("cp.async.commit_group;" ::: "memory")
#define CP_WAIT(n)  asm volatile("cp.async.wait_group %0;" :: "n"(n) : "memory")

// ---------------------------------------------------------------------------
// f2h: fp32 -> fp16 bulk convert (float4 -> 2x half2)
// ---------------------------------------------------------------------------
__global__ void f2h(const float* __restrict__ s, half* __restrict__ d, int n4)
{
    int i = blockIdx.x * blockDim.x + threadIdx.x;
    if (i >= n4) return;
    float4 v = ((const float4*)s)[i];
    ((half2*)d)[2 * i]     = __floats2half2_rn(v.x, v.y);
    ((half2*)d)[2 * i + 1] = __floats2half2_rn(v.z, v.w);
}

// ===========================================================================
// fp16 GEMM, cp.async 3-stage: C[M,N] = A[M,K] @ B[K,N], fp16 in / fp32 out.
// CTA 128x128, BK=32, 256 thr, warps 2(M)x4(N), warp tile 64x32.
// A smem stride 80B, B smem stride 272B (ldmatrix conflict-free).
// ===========================================================================
#define AST_B  (128 * 80)           // 10240
#define BST_B  (32 * 272)           // 8704
#define STAGE_B (AST_B + BST_B)     // 18944
#define GSMEM  (3 * STAGE_B)        // 56832

__device__ __forceinline__ void gemm_core_h(const half* __restrict__ Ah,
                                            const half* __restrict__ Bh,
                                            float* __restrict__ C,
                                            int N, int K, int bm, int bn)
{
    extern __shared__ char smem[];
    uint32_t sb = smem_u32(smem);
    int tid = threadIdx.x, lane = tid & 31, wid = tid >> 5;
    int wm = (wid >> 2) * 64, wn = (wid & 3) * 32;

    float acc[4][4][4];
#pragma unroll
    for (int mi = 0; mi < 4; mi++)
#pragma unroll
        for (int ni = 0; ni < 4; ni++)
#pragma unroll
            for (int c = 0; c < 4; c++) acc[mi][ni][c] = 0.f;

    auto issue = [&](int s) {
        int k0 = s << 5;
        uint32_t base = sb + (s % 3) * STAGE_B;
#pragma unroll
        for (int l = 0; l < 2; l++) {
            int idx = tid + l * 256;
            int row = idx >> 2, ch = idx & 3;
            cpasync16(base + row * 80 + ch * 16,
                      (const char*)Ah + ((size_t)(bm + row) * K + k0) * 2 + ch * 16);
            int br = idx >> 4, bch = idx & 15;
            cpasync16(base + AST_B + br * 272 + bch * 16,
                      (const char*)Bh + ((size_t)(k0 + br) * N + bn) * 2 + bch * 16);
        }
    };

    int niter = K >> 5;
    issue(0); CP_COMMIT();
    issue(1); CP_COMMIT();

    for (int i = 0; i < niter; i++) {
        __syncthreads();                     // all done with buffer (i+2)%3
        if (i + 2 < niter) { issue(i + 2); CP_COMMIT(); CP_WAIT(2); }
        else if (i + 1 < niter) CP_WAIT(1);
        else CP_WAIT(0);
        __syncthreads();                     // stage i visible to all

        uint32_t ab = sb + (i % 3) * STAGE_B;
        uint32_t bb = ab + AST_B;
#pragma unroll
        for (int ks = 0; ks < 2; ks++) {
            uint32_t af[4][4], bf[2][4];
#pragma unroll
            for (int mi = 0; mi < 4; mi++)
                ldmx4(af[mi], ab + (wm + mi * 16 + (lane & 15)) * 80
                               + ks * 32 + ((lane >> 4) << 4));
#pragma unroll
            for (int nh = 0; nh < 2; nh++)
                ldmx4t(bf[nh], bb + (ks * 16 + (lane & 7) + ((lane >> 3) & 1) * 8) * 272
                                + (wn + nh * 16 + ((lane >> 4) << 3)) * 2);
#pragma unroll
            for (int mi = 0; mi < 4; mi++)
#pragma unroll
                for (int ni = 0; ni < 4; ni++)
                    mma_f16(acc[mi][ni], af[mi], &bf[ni >> 1][(ni & 1) * 2]);
        }
    }

    int r = bm + wm + (lane >> 2);
    int c = bn + wn + (lane & 3) * 2;
#pragma unroll
    for (int mi = 0; mi < 4; mi++) {
#pragma unroll
        for (int ni = 0; ni < 4; ni++) {
            *(float2*)(C + (size_t)(r + mi * 16)     * N + c + ni * 8) =
                make_float2(acc[mi][ni][0], acc[mi][ni][1]);
            *(float2*)(C + (size_t)(r + mi * 16 + 8) * N + c + ni * 8) =
                make_float2(acc[mi][ni][2], acc[mi][ni][3]);
        }
    }
}

__global__ __launch_bounds__(256, 2) void qkv_mma(const half* __restrict__ xh,
                                                  float* __restrict__ q,
                                                  float* __restrict__ k,
                                                  float* __restrict__ v)
{
    int bx = blockIdx.x, bm = blockIdx.y << 7;
    const half* B; float* C; int N, bn;
    if (bx < 16)      { B = g_wqh; C = q; N = DIM;   bn = bx << 7; }
    else if (bx < 20) { B = g_wkh; C = k; N = KVDIM; bn = (bx - 16) << 7; }
    else              { B = g_wvh; C = v; N = KVDIM; bn = (bx - 20) << 7; }
    gemm_core_h(xh, B, C, N, DIM, bm, bn);
}

__global__ __launch_bounds__(256, 2) void out_mma(const half* __restrict__ Ah,
                                                  const half* __restrict__ Bh,
                                                  float* __restrict__ C,
                                                  int N, int K)
{
    gemm_core_h(Ah, Bh, C, N, K, blockIdx.y << 7, blockIdx.x << 7);
}

// ---------------------------------------------------------------------------
// RoPE: fp32 in -> fp16 out. q variant folds 1/sqrt(HD) scale.
// ---------------------------------------------------------------------------
__global__ void rope_qh(const float* __restrict__ src, half* __restrict__ dst,
                        const float* __restrict__ c, const float* __restrict__ s)
{
    int idx = blockIdx.x * blockDim.x + threadIdx.x;
    if (idx >= MS * NH * 64) return;
    int p  = idx & 63;
    int h  = (idx >> 6) & 15;
    int bs = idx >> 10;
    int sq = bs & (SEQ - 1);
    float cv = c[sq * 64 + p], sv = s[sq * 64 + p];
    const float* b = src + (size_t)bs * DIM + h * HD + 2 * p;
    float xr = b[0], xi = b[1];
    const float sc = 0.08838834764831845f;
    *(half2*)(dst + (size_t)bs * DIM + h * HD + 2 * p) =
        __floats2half2_rn((xr * cv - xi * sv) * sc, (xr * sv + xi * cv) * sc);
}
__global__ void rope_kh(const float* __restrict__ src, half* __restrict__ dst,
                        const float* __restrict__ c, const float* __restrict__ s)
{
    int idx = blockIdx.x * blockDim.x + threadIdx.x;
    if (idx >= MS * NKV * 64) return;
    int p  = idx & 63;
    int h  = (idx >> 6) & 3;
    int bs = idx >> 8;
    int sq = bs & (SEQ - 1);
    float cv = c[sq * 64 + p], sv = s[sq * 64 + p];
    const float* b = src + (size_t)bs * KVDIM + h * HD + 2 * p;
    float xr = b[0], xi = b[1];
    *(half2*)(dst + (size_t)bs * KVDIM + h * HD + 2 * p) =
        __floats2half2_rn(xr * cv - xi * sv, xr * sv + xi * cv);
}

// ===========================================================================
// FA2-style flash attention: CTA = 128 q-rows x one (b,h), 8 warps x 16 rows.
// S stays in registers (C-frag == A-frag identity); softmax via quad shuffles;
// K/V fp16 double-buffered via cp.async; output written as fp16 (feeds Wo GEMM).
// ===========================================================================
#define AQ_STR 272                  // bytes per row (ldmatrix conflict-free)
#define Q_OFF  0                    // 128*272 = 34816
#define K_OFF  34816                // 2 stages x 64*272
#define V_OFF  69632                // 2 stages x 64*272
#define ATT_SMEM 104448

__global__ __launch_bounds__(256, 1) void attn_fa2(const half* __restrict__ Qh,
                                                   const half* __restrict__ Kh,
                                                   const half* __restrict__ Vh,
                                                   half* __restrict__ Oh)
{
    extern __shared__ char smem[];
    uint32_t sbu = smem_u32(smem);

    int tid = threadIdx.x, lane = tid & 31, wid = tid >> 5;
    int wm = wid * 16;
    int mblk = gridDim.x - 1 - blockIdx.x;   // long CTAs first
    int bh = blockIdx.y;
    int b = bh >> 4, h = bh & 15;
    int g = h >> 2;
    int m0 = mblk * 128;

    const char* qsrc = (const char*)Qh + ((size_t)(b * SEQ + m0) * DIM + h * HD) * 2;

    // ---- issue Q (group 0) ----
#pragma unroll
    for (int l = 0; l < 8; l++) {
        int idx = tid + l * 256;
        int row = idx >> 4, ch = idx & 15;
        cpasync16(sbu + Q_OFF + row * 272 + ch * 16,
                  qsrc + (size_t)row * DIM * 2 + ch * 16);
    }
    CP_COMMIT();

    auto issue_kv = [&](int it) {
        int n0 = it * 64, st = it & 1;
        const char* ks = (const char*)Kh + ((size_t)(b * SEQ + n0) * KVDIM + g * HD) * 2;
        const char* vs = (const char*)Vh + ((size_t)(b * SEQ + n0) * KVDIM + g * HD) * 2;
        uint32_t kd = sbu + K_OFF + st * 17408;
        uint32_t vd = sbu + V_OFF + st * 17408;
#pragma unroll
        for (int l = 0; l < 4; l++) {
            int idx = tid + l * 256;
            int row = idx >> 4, ch = idx & 15;
            cpasync16(kd + row * 272 + ch * 16, ks + (size_t)row * KVDIM * 2 + ch * 16);
            cpasync16(vd + row * 272 + ch * 16, vs + (size_t)row * KVDIM * 2 + ch * 16);
        }
    };
    issue_kv(0); CP_COMMIT();       // group 1

    CP_WAIT(1);                     // Q done (KV0 may be pending)
    __syncthreads();

    // ---- Q fragments to registers (once) ----
    uint32_t qf[8][4];
#pragma unroll
    for (int ks = 0; ks < 8; ks++)
        ldmx4(qf[ks], sbu + Q_OFF + (wm + (lane & 15)) * 272
                       + ks * 32 + ((lane >> 4) << 4));

    float oacc[16][4];
#pragma unroll
    for (int t = 0; t < 16; t++)
#pragma unroll
        for (int c = 0; c < 4; c++) oacc[t][c] = 0.f;
    float m_lo = -1e30f, m_hi = -1e30f, l_lo = 0.f, l_hi = 0.f;

    int niter = 2 * mblk + 2;
    for (int i = 0; i < niter; i++) {
        __syncthreads();                         // all done reading buf (i+1)&1
        if (i + 1 < niter) { issue_kv(i + 1); CP_COMMIT(); CP_WAIT(1); }
        else CP_WAIT(0);
        __syncthreads();                         // KV stage i visible

        int n0 = i * 64;
        uint32_t kb = sbu + K_OFF + (i & 1) * 17408;
        uint32_t vb = sbu + V_OFF + (i & 1) * 17408;

        if (n0 <= m0 + wm + 15) {                // warp-uniform skip
            // ---- S = Q K^T ----
            float sacc[8][4];
#pragma unroll
            for (int t = 0; t < 8; t++)
#pragma unroll
                for (int c = 0; c < 4; c++) sacc[t][c] = 0.f;
#pragma unroll
            for (int ks = 0; ks < 8; ks++) {
                uint32_t bf[4][4];
#pragma unroll
                for (int nh = 0; nh < 4; nh++)
                    ldmx4(bf[nh], kb + (nh * 16 + ((lane >> 4) << 3) + (lane & 7)) * 272
                                   + ks * 32 + (((lane >> 3) & 1) << 4));
#pragma unroll
                for (int t = 0; t < 8; t++)
                    mma_f16(sacc[t], qf[ks], &bf[t >> 1][(t & 1) * 2]);
            }
            // ---- causal mask (only near diagonal) ----
            if (n0 + 63 > m0 + wm) {
                int r0 = m0 + wm + (lane >> 2);
#pragma unroll
                for (int t = 0; t < 8; t++) {
                    int c0 = n0 + 8 * t + 2 * (lane & 3);
                    if (c0     > r0)     sacc[t][0] = -1e30f;
                    if (c0 + 1 > r0)     sacc[t][1] = -1e30f;
                    if (c0     > r0 + 8) sacc[t][2] = -1e30f;
                    if (c0 + 1 > r0 + 8) sacc[t][3] = -1e30f;
                }
            }
            // ---- register online softmax (quad shuffles) ----
            float rm_lo = -1e30f, rm_hi = -1e30f;
#pragma unroll
            for (int t = 0; t < 8; t++) {
                rm_lo = fmaxf(rm_lo, fmaxf(sacc[t][0], sacc[t][1]));
                rm_hi = fmaxf(rm_hi, fmaxf(sacc[t][2], sacc[t][3]));
            }
            rm_lo = fmaxf(rm_lo, __shfl_xor_sync(0xffffffffu, rm_lo, 1));
            rm_lo = fmaxf(rm_lo, __shfl_xor_sync(0xffffffffu, rm_lo, 2));
            rm_hi = fmaxf(rm_hi, __shfl_xor_sync(0xffffffffu, rm_hi, 1));
            rm_hi = fmaxf(rm_hi, __shfl_xor_sync(0xffffffffu, rm_hi, 2));
            float nm_lo = fmaxf(m_lo, rm_lo), nm_hi = fmaxf(m_hi, rm_hi);
            float cf_lo = __expf(m_lo - nm_lo), cf_hi = __expf(m_hi - nm_hi);
            m_lo = nm_lo; m_hi = nm_hi;

            float sum_lo = 0.f, sum_hi = 0.f;
            uint32_t pf[4][4];
#pragma unroll
            for (int t = 0; t < 8; t++) {
                float p0 = __expf(sacc[t][0] - nm_lo);
                float p1 = __expf(sacc[t][1] - nm_lo);
                float p2 = __expf(sacc[t][2] - nm_hi);
                float p3 = __expf(sacc[t][3] - nm_hi);
                sum_lo += p0 + p1; sum_hi += p2 + p3;
                half2 h01 = __floats2half2_rn(p0, p1);
                half2 h23 = __floats2half2_rn(p2, p3);
                pf[t >> 1][(t & 1) * 2]     = *(uint32_t*)&h01;
                pf[t >> 1][(t & 1) * 2 + 1] = *(uint32_t*)&h23;
            }
            sum_lo += __shfl_xor_sync(0xffffffffu, sum_lo, 1);
            sum_lo += __shfl_xor_sync(0xffffffffu, sum_lo, 2);
            sum_hi += __shfl_xor_sync(0xffffffffu, sum_hi, 1);
            sum_hi += __shfl_xor_sync(0xffffffffu, sum_hi, 2);
            l_lo = l_lo * cf_lo + sum_lo;
            l_hi = l_hi * cf_hi + sum_hi;
#pragma unroll
            for (int t = 0; t < 16; t++) {
                oacc[t][0] *= cf_lo; oacc[t][1] *= cf_lo;
                oacc[t][2] *= cf_hi; oacc[t][3] *= cf_hi;
            }
            // ---- O += P V ----
#pragma unroll
            for (int ks = 0; ks < 4; ks++) {
                uint32_t bv[8][4];
#pragma unroll
                for (int nh = 0; nh < 8; nh++)
                    ldmx4t(bv[nh], vb + (ks * 16 + (lane & 7) + ((lane >> 3) & 1) * 8) * 272
                                    + (nh * 16 + ((lane >> 4) << 3)) * 2);
#pragma unroll
                for (int t = 0; t < 16; t++)
                    mma_f16(oacc[t], pf[ks], &bv[t >> 1][(t & 1) * 2]);
            }
        }
    }

    // ---- finalize: write fp16 output ----
    float inv_lo = 1.f / l_lo, inv_hi = 1.f / l_hi;
    int r0 = m0 + wm + (lane >> 2);
    half* ob0 = Oh + (size_t)(b * SEQ + r0) * DIM + h * HD;
    half* ob1 = ob0 + (size_t)8 * DIM;
#pragma unroll
    for (int t = 0; t < 16; t++) {
        int cb = 8 * t + 2 * (lane & 3);
        half2 w0 = __floats2half2_rn(oacc[t][0] * inv_lo, oacc[t][1] * inv_lo);
        half2 w1 = __floats2half2_rn(oacc[t][2] * inv_hi, oacc[t][3] * inv_hi);
        *(half2*)(ob0 + cb) = w0;
        *(half2*)(ob1 + cb) = w1;
    }
}

// ---------------------------------------------------------------------------
extern "C" void kernel_launch(void* const* d_in, const int* in_sizes, int n_in,
                              void* d_out, int out_size)
{
    const float* x  = (const float*)d_in[0];
    const float* fc = (const float*)d_in[1];
    const float* fs = (const float*)d_in[2];
    const float* Wq = (const float*)d_in[3];
    const float* Wk = (const float*)d_in[4];
    const float* Wv = (const float*)d_in[5];
    const float* Wo = (const float*)d_in[6];
    float* out = (float*)d_out;

    float *q, *k, *v;
    half *xh, *wqh, *wkh, *wvh, *woh, *qh, *kh, *vh, *atth;
    cudaGetSymbolAddress((void**)&q,    g_q);
    cudaGetSymbolAddress((void**)&k,    g_k);
    cudaGetSymbolAddress((void**)&v,    g_v);
    cudaGetSymbolAddress((void**)&xh,   g_xh);
    cudaGetSymbolAddress((void**)&wqh,  g_wqh);
    cudaGetSymbolAddress((void**)&wkh,  g_wkh);
    cudaGetSymbolAddress((void**)&wvh,  g_wvh);
    cudaGetSymbolAddress((void**)&woh,  g_woh);
    cudaGetSymbolAddress((void**)&qh,   g_qh);
    cudaGetSymbolAddress((void**)&kh,   g_kh);
    cudaGetSymbolAddress((void**)&vh,   g_vh);
    cudaGetSymbolAddress((void**)&atth, g_atth);

    cudaFuncSetAttribute(qkv_mma,  cudaFuncAttributeMaxDynamicSharedMemorySize, GSMEM);
    cudaFuncSetAttribute(out_mma,  cudaFuncAttributeMaxDynamicSharedMemorySize, GSMEM);
    cudaFuncSetAttribute(attn_fa2, cudaFuncAttributeMaxDynamicSharedMemorySize, ATT_SMEM);

    // fp32 -> fp16 operand converts
    f2h<<<(MS * DIM / 4 + 255) / 256, 256>>>(x,  xh,  MS * DIM / 4);
    f2h<<<(DIM * DIM / 4 + 255) / 256, 256>>>(Wq, wqh, DIM * DIM / 4);
    f2h<<<(DIM * KVDIM / 4 + 255) / 256, 256>>>(Wk, wkh, DIM * KVDIM / 4);
    f2h<<<(DIM * KVDIM / 4 + 255) / 256, 256>>>(Wv, wvh, DIM * KVDIM / 4);
    f2h<<<(DIM * DIM / 4 + 255) / 256, 256>>>(Wo, woh, DIM * DIM / 4);

    // fused QKV projections (fp16 in, fp32 out)
    qkv_mma<<<dim3(24, MS / 128), 256, GSMEM>>>(xh, q, k, v);

    // RoPE -> fp16 (q pre-scaled); V convert
    rope_qh<<<(MS * NH  * 64 + 255) / 256, 256>>>(q, qh, fc, fs);
    rope_kh<<<(MS * NKV * 64 + 255) / 256, 256>>>(k, kh, fc, fs);
    f2h<<<(MS * KVDIM / 4 + 255) / 256, 256>>>(v, vh, MS * KVDIM / 4);

    // flash attention (fp16, register softmax) -> fp16 att
    attn_fa2<<<dim3(SEQ / 128, BATCH * NH), 256, ATT_SMEM>>>(qh, kh, vh, atth);

    // output projection
    out_mma<<<dim3(DIM / 128, MS / 128), 256, GSMEM>>>(atth, woh, out, DIM, DIM);
}

// round 12
// speedup vs baseline: 7.0323x; 1.0010x over previous
#include <cuda_runtime.h>
#include <cuda_fp16.h>
#include <cstdint>

#define BATCH 2
#define SEQ   2048
#define DIM   2048
#define NH    16
#define NKV   4
#define HD    128
#define KVDIM (NKV*HD)      // 512
#define MS    (BATCH*SEQ)   // 4096

// ---- scratch (device globals; no allocation allowed) ----
__device__ half  g_xh [MS * DIM];
__device__ half  g_wqh[DIM * DIM];
__device__ half  g_wkh[DIM * KVDIM];
__device__ half  g_wvh[DIM * KVDIM];
__device__ half  g_woh[DIM * DIM];
__device__ half  g_qh [MS * DIM];
__device__ half  g_kh [MS * KVDIM];
__device__ half  g_vh [MS * KVDIM];
__device__ half  g_atth[MS * DIM];

// ===========================================================================
// primitives
// ===========================================================================
__device__ __forceinline__ uint32_t smem_u32(const void* p) {
    uint32_t a;
    asm("{ .reg .u64 t; cvta.to.shared.u64 t, %1; cvt.u32.u64 %0, t; }"
        : "=r"(a) : "l"(p));
    return a;
}
__device__ __forceinline__ void ldmx4(uint32_t* r, uint32_t addr) {
    asm volatile("ldmatrix.sync.aligned.m8n8.x4.shared.b16 {%0,%1,%2,%3}, [%4];"
                 : "=r"(r[0]), "=r"(r[1]), "=r"(r[2]), "=r"(r[3]) : "r"(addr));
}
__device__ __forceinline__ void ldmx4t(uint32_t* r, uint32_t addr) {
    asm volatile("ldmatrix.sync.aligned.m8n8.x4.trans.shared.b16 {%0,%1,%2,%3}, [%4];"
                 : "=r"(r[0]), "=r"(r[1]), "=r"(r[2]), "=r"(r[3]) : "r"(addr));
}
__device__ __forceinline__ void mma_f16(float* c, const uint32_t* a,
                                        const uint32_t* b) {
    asm volatile(
        "mma.sync.aligned.m16n8k16.row.col.f32.f16.f16.f32 "
        "{%0,%1,%2,%3}, {%4,%5,%6,%7}, {%8,%9}, {%0,%1,%2,%3};"
        : "+f"(c[0]), "+f"(c[1]), "+f"(c[2]), "+f"(c[3])
        : "r"(a[0]), "r"(a[1]), "r"(a[2]), "r"(a[3]), "r"(b[0]), "r"(b[1]));
}
__device__ __forceinline__ void cpasync16(uint32_t dst, const void* src) {
    asm volatile("cp.async.cg.shared.global [%0], [%1], 16;"
                 :: "r"(dst), "l"(src));
}
#define CP_COMMIT() asm volatile("cp.async.commit_group;" ::: "memory")
#define CP_WAIT(n)  asm volatile("cp.async.wait_group %0;" :: "n"(n) : "memory")

// ---------------------------------------------------------------------------
// f2h_multi: one launch converting all 5 fp32 operands to fp16.
// grid.y selects segment; grid.x sized for the largest segment.
// ---------------------------------------------------------------------------
__global__ void f2h_multi(const float* __restrict__ x,  half* __restrict__ xh,
                          const float* __restrict__ wq, half* __restrict__ wqh,
                          const float* __restrict__ wk, half* __restrict__ wkh,
                          const float* __restrict__ wv, half* __restrict__ wvh,
                          const float* __restrict__ wo, half* __restrict__ woh)
{
    const float* s; half* d; int n4;
    switch (blockIdx.y) {
        case 0: s = x;  d = xh;  n4 = MS * DIM / 4;    break;
        case 1: s = wq; d = wqh; n4 = DIM * DIM / 4;   break;
        case 2: s = wk; d = wkh; n4 = DIM * KVDIM / 4; break;
        case 3: s = wv; d = wvh; n4 = DIM * KVDIM / 4; break;
        default:s = wo; d = woh; n4 = DIM * DIM / 4;   break;
    }
    int i = blockIdx.x * blockDim.x + threadIdx.x;
    if (i >= n4) return;
    float4 v = ((const float4*)s)[i];
    ((half2*)d)[2 * i]     = __floats2half2_rn(v.x, v.y);
    ((half2*)d)[2 * i + 1] = __floats2half2_rn(v.z, v.w);
}

// ===========================================================================
// fp16 GEMM core, cp.async 3-stage. CTA 128x128, BK=32, 256 thr,
// warps 2(M)x4(N), warp tile 64x32.
// Epilogue modes: 0 = fp32 store; 1 = RoPE+scale -> fp16 (q);
//                 2 = RoPE -> fp16 (k); 3 = plain fp16 (v).
// ===========================================================================
#define AST_B  (128 * 80)           // 10240
#define BST_B  (32 * 272)           // 8704
#define STAGE_B (AST_B + BST_B)     // 18944
#define GSMEM  (3 * STAGE_B)        // 56832

__device__ __forceinline__ void gemm_core_h(const half* __restrict__ Ah,
                                            const half* __restrict__ Bh,
                                            float* __restrict__ Cf,
                                            half* __restrict__ Ch,
                                            int N, int K, int bm, int bn,
                                            int mode,
                                            const float* __restrict__ fc,
                                            const float* __restrict__ fs)
{
    extern __shared__ char smem[];
    uint32_t sb = smem_u32(smem);
    int tid = threadIdx.x, lane = tid & 31, wid = tid >> 5;
    int wm = (wid >> 2) * 64, wn = (wid & 3) * 32;

    float acc[4][4][4];
#pragma unroll
    for (int mi = 0; mi < 4; mi++)
#pragma unroll
        for (int ni = 0; ni < 4; ni++)
#pragma unroll
            for (int c = 0; c < 4; c++) acc[mi][ni][c] = 0.f;

    auto issue = [&](int s) {
        int k0 = s << 5;
        uint32_t base = sb + (s % 3) * STAGE_B;
#pragma unroll
        for (int l = 0; l < 2; l++) {
            int idx = tid + l * 256;
            int row = idx >> 2, ch = idx & 3;
            cpasync16(base + row * 80 + ch * 16,
                      (const char*)Ah + ((size_t)(bm + row) * K + k0) * 2 + ch * 16);
            int br = idx >> 4, bch = idx & 15;
            cpasync16(base + AST_B + br * 272 + bch * 16,
                      (const char*)Bh + ((size_t)(k0 + br) * N + bn) * 2 + bch * 16);
        }
    };

    int niter = K >> 5;
    issue(0); CP_COMMIT();
    issue(1); CP_COMMIT();

    for (int i = 0; i < niter; i++) {
        __syncthreads();                     // all done with buffer (i+2)%3
        if (i + 2 < niter) { issue(i + 2); CP_COMMIT(); CP_WAIT(2); }
        else if (i + 1 < niter) CP_WAIT(1);
        else CP_WAIT(0);
        __syncthreads();                     // stage i visible to all

        uint32_t ab = sb + (i % 3) * STAGE_B;
        uint32_t bb = ab + AST_B;
#pragma unroll
        for (int ks = 0; ks < 2; ks++) {
            uint32_t af[4][4], bf[2][4];
#pragma unroll
            for (int mi = 0; mi < 4; mi++)
                ldmx4(af[mi], ab + (wm + mi * 16 + (lane & 15)) * 80
                               + ks * 32 + ((lane >> 4) << 4));
#pragma unroll
            for (int nh = 0; nh < 2; nh++)
                ldmx4t(bf[nh], bb + (ks * 16 + (lane & 7) + ((lane >> 3) & 1) * 8) * 272
                                + (wn + nh * 16 + ((lane >> 4) << 3)) * 2);
#pragma unroll
            for (int mi = 0; mi < 4; mi++)
#pragma unroll
                for (int ni = 0; ni < 4; ni++)
                    mma_f16(acc[mi][ni], af[mi], &bf[ni >> 1][(ni & 1) * 2]);
        }
    }

    int r = bm + wm + (lane >> 2);
    int c = bn + wn + (lane & 3) * 2;

    if (mode == 0) {
#pragma unroll
        for (int mi = 0; mi < 4; mi++) {
#pragma unroll
            for (int ni = 0; ni < 4; ni++) {
                *(float2*)(Cf + (size_t)(r + mi * 16)     * N + c + ni * 8) =
                    make_float2(acc[mi][ni][0], acc[mi][ni][1]);
                *(float2*)(Cf + (size_t)(r + mi * 16 + 8) * N + c + ni * 8) =
                    make_float2(acc[mi][ni][2], acc[mi][ni][3]);
            }
        }
        return;
    }

    // fp16 output epilogue (optionally with fused RoPE).
    // Thread owns column pairs (cg, cg+1), cg even — exactly RoPE's (2p, 2p+1).
    const float sc = 0.08838834764831845f;  // 1/sqrt(128)
#pragma unroll
    for (int mi = 0; mi < 4; mi++) {
        int row0 = r + mi * 16, row1 = row0 + 8;
#pragma unroll
        for (int ni = 0; ni < 4; ni++) {
            int cg = c + ni * 8;
            float a0 = acc[mi][ni][0], a1 = acc[mi][ni][1];
            float a2 = acc[mi][ni][2], a3 = acc[mi][ni][3];
            if (mode < 3) {
                int p = (cg & 127) >> 1;
                int sq0 = row0 & (SEQ - 1), sq1 = row1 & (SEQ - 1);
                float c0 = fc[sq0 * 64 + p], s0 = fs[sq0 * 64 + p];
                float c1 = fc[sq1 * 64 + p], s1 = fs[sq1 * 64 + p];
                float r0 = a0 * c0 - a1 * s0, i0 = a0 * s0 + a1 * c0;
                float r1 = a2 * c1 - a3 * s1, i1 = a2 * s1 + a3 * c1;
                if (mode == 1) { r0 *= sc; i0 *= sc; r1 *= sc; i1 *= sc; }
                a0 = r0; a1 = i0; a2 = r1; a3 = i1;
            }
            *(half2*)(Ch + (size_t)row0 * N + cg) = __floats2half2_rn(a0, a1);
            *(half2*)(Ch + (size_t)row1 * N + cg) = __floats2half2_rn(a2, a3);
        }
    }
}

// Fused QKV projection + RoPE: grid.x = 16 (q) + 4 (k) + 4 (v) column blocks.
__global__ __launch_bounds__(256, 2) void qkv_mma(const half* __restrict__ xh,
                                                  const float* __restrict__ fc,
                                                  const float* __restrict__ fs)
{
    int bx = blockIdx.x, bm = blockIdx.y << 7;
    const half* B; half* D; int N, bn, mode;
    if (bx < 16)      { B = g_wqh; D = g_qh; N = DIM;   bn = bx << 7;        mode = 1; }
    else if (bx < 20) { B = g_wkh; D = g_kh; N = KVDIM; bn = (bx - 16) << 7; mode = 2; }
    else              { B = g_wvh; D = g_vh; N = KVDIM; bn = (bx - 20) << 7; mode = 3; }
    gemm_core_h(xh, B, nullptr, D, N, DIM, bm, bn, mode, fc, fs);
}

__global__ __launch_bounds__(256, 2) void out_mma(const half* __restrict__ Ah,
                                                  const half* __restrict__ Bh,
                                                  float* __restrict__ C,
                                                  int N, int K)
{
    gemm_core_h(Ah, Bh, C, nullptr, N, K, blockIdx.y << 7, blockIdx.x << 7,
                0, nullptr, nullptr);
}

// ===========================================================================
// FA2-style flash attention: CTA = 128 q-rows x one (b,h), 8 warps x 16 rows.
// S stays in registers (C-frag == A-frag identity); softmax via quad shuffles;
// K/V fp16 double-buffered via cp.async; output written as fp16 (feeds Wo GEMM).
// ===========================================================================
#define Q_OFF  0                    // 128*272 = 34816
#define K_OFF  34816                // 2 stages x 64*272
#define V_OFF  69632                // 2 stages x 64*272
#define ATT_SMEM 104448

__global__ __launch_bounds__(256, 1) void attn_fa2(const half* __restrict__ Qh,
                                                   const half* __restrict__ Kh,
                                                   const half* __restrict__ Vh,
                                                   half* __restrict__ Oh)
{
    extern __shared__ char smem[];
    uint32_t sbu = smem_u32(smem);

    int tid = threadIdx.x, lane = tid & 31, wid = tid >> 5;
    int wm = wid * 16;
    int mblk = gridDim.x - 1 - blockIdx.x;   // long CTAs first
    int bh = blockIdx.y;
    int b = bh >> 4, h = bh & 15;
    int g = h >> 2;
    int m0 = mblk * 128;

    const char* qsrc = (const char*)Qh + ((size_t)(b * SEQ + m0) * DIM + h * HD) * 2;

    // ---- issue Q (group 0) ----
#pragma unroll
    for (int l = 0; l < 8; l++) {
        int idx = tid + l * 256;
        int row = idx >> 4, ch = idx & 15;
        cpasync16(sbu + Q_OFF + row * 272 + ch * 16,
                  qsrc + (size_t)row * DIM * 2 + ch * 16);
    }
    CP_COMMIT();

    auto issue_kv = [&](int it) {
        int n0 = it * 64, st = it & 1;
        const char* ks = (const char*)Kh + ((size_t)(b * SEQ + n0) * KVDIM + g * HD) * 2;
        const char* vs = (const char*)Vh + ((size_t)(b * SEQ + n0) * KVDIM + g * HD) * 2;
        uint32_t kd = sbu + K_OFF + st * 17408;
        uint32_t vd = sbu + V_OFF + st * 17408;
#pragma unroll
        for (int l = 0; l < 4; l++) {
            int idx = tid + l * 256;
            int row = idx >> 4, ch = idx & 15;
            cpasync16(kd + row * 272 + ch * 16, ks + (size_t)row * KVDIM * 2 + ch * 16);
            cpasync16(vd + row * 272 + ch * 16, vs + (size_t)row * KVDIM * 2 + ch * 16);
        }
    };
    issue_kv(0); CP_COMMIT();       // group 1

    CP_WAIT(1);                     // Q done (KV0 may be pending)
    __syncthreads();

    // ---- Q fragments to registers (once) ----
    uint32_t qf[8][4];
#pragma unroll
    for (int ks = 0; ks < 8; ks++)
        ldmx4(qf[ks], sbu + Q_OFF + (wm + (lane & 15)) * 272
                       + ks * 32 + ((lane >> 4) << 4));

    float oacc[16][4];
#pragma unroll
    for (int t = 0; t < 16; t++)
#pragma unroll
        for (int c = 0; c < 4; c++) oacc[t][c] = 0.f;
    float m_lo = -1e30f, m_hi = -1e30f, l_lo = 0.f, l_hi = 0.f;

    int niter = 2 * mblk + 2;
    for (int i = 0; i < niter; i++) {
        __syncthreads();                         // all done reading buf (i+1)&1
        if (i + 1 < niter) { issue_kv(i + 1); CP_COMMIT(); CP_WAIT(1); }
        else CP_WAIT(0);
        __syncthreads();                         // KV stage i visible

        int n0 = i * 64;
        uint32_t kb = sbu + K_OFF + (i & 1) * 17408;
        uint32_t vb = sbu + V_OFF + (i & 1) * 17408;

        if (n0 <= m0 + wm + 15) {                // warp-uniform skip
            // ---- S = Q K^T ----
            float sacc[8][4];
#pragma unroll
            for (int t = 0; t < 8; t++)
#pragma unroll
                for (int c = 0; c < 4; c++) sacc[t][c] = 0.f;
#pragma unroll
            for (int ks = 0; ks < 8; ks++) {
                uint32_t bf[4][4];
#pragma unroll
                for (int nh = 0; nh < 4; nh++)
                    ldmx4(bf[nh], kb + (nh * 16 + ((lane >> 4) << 3) + (lane & 7)) * 272
                                   + ks * 32 + (((lane >> 3) & 1) << 4));
#pragma unroll
                for (int t = 0; t < 8; t++)
                    mma_f16(sacc[t], qf[ks], &bf[t >> 1][(t & 1) * 2]);
            }
            // ---- causal mask (only near diagonal) ----
            if (n0 + 63 > m0 + wm) {
                int r0 = m0 + wm + (lane >> 2);
#pragma unroll
                for (int t = 0; t < 8; t++) {
                    int c0 = n0 + 8 * t + 2 * (lane & 3);
                    if (c0     > r0)     sacc[t][0] = -1e30f;
                    if (c0 + 1 > r0)     sacc[t][1] = -1e30f;
                    if (c0     > r0 + 8) sacc[t][2] = -1e30f;
                    if (c0 + 1 > r0 + 8) sacc[t][3] = -1e30f;
                }
            }
            // ---- register online softmax (quad shuffles) ----
            float rm_lo = -1e30f, rm_hi = -1e30f;
#pragma unroll
            for (int t = 0; t < 8; t++) {
                rm_lo = fmaxf(rm_lo, fmaxf(sacc[t][0], sacc[t][1]));
                rm_hi = fmaxf(rm_hi, fmaxf(sacc[t][2], sacc[t][3]));
            }
            rm_lo = fmaxf(rm_lo, __shfl_xor_sync(0xffffffffu, rm_lo, 1));
            rm_lo = fmaxf(rm_lo, __shfl_xor_sync(0xffffffffu, rm_lo, 2));
            rm_hi = fmaxf(rm_hi, __shfl_xor_sync(0xffffffffu, rm_hi, 1));
            rm_hi = fmaxf(rm_hi, __shfl_xor_sync(0xffffffffu, rm_hi, 2));
            float nm_lo = fmaxf(m_lo, rm_lo), nm_hi = fmaxf(m_hi, rm_hi);
            float cf_lo = __expf(m_lo - nm_lo), cf_hi = __expf(m_hi - nm_hi);
            m_lo = nm_lo; m_hi = nm_hi;

            float sum_lo = 0.f, sum_hi = 0.f;
            uint32_t pf[4][4];
#pragma unroll
            for (int t = 0; t < 8; t++) {
                float p0 = __expf(sacc[t][0] - nm_lo);
                float p1 = __expf(sacc[t][1] - nm_lo);
                float p2 = __expf(sacc[t][2] - nm_hi);
                float p3 = __expf(sacc[t][3] - nm_hi);
                sum_lo += p0 + p1; sum_hi += p2 + p3;
                half2 h01 = __floats2half2_rn(p0, p1);
                half2 h23 = __floats2half2_rn(p2, p3);
                pf[t >> 1][(t & 1) * 2]     = *(uint32_t*)&h01;
                pf[t >> 1][(t & 1) * 2 + 1] = *(uint32_t*)&h23;
            }
            sum_lo += __shfl_xor_sync(0xffffffffu, sum_lo, 1);
            sum_lo += __shfl_xor_sync(0xffffffffu, sum_lo, 2);
            sum_hi += __shfl_xor_sync(0xffffffffu, sum_hi, 1);
            sum_hi += __shfl_xor_sync(0xffffffffu, sum_hi, 2);
            l_lo = l_lo * cf_lo + sum_lo;
            l_hi = l_hi * cf_hi + sum_hi;
#pragma unroll
            for (int t = 0; t < 16; t++) {
                oacc[t][0] *= cf_lo; oacc[t][1] *= cf_lo;
                oacc[t][2] *= cf_hi; oacc[t][3] *= cf_hi;
            }
            // ---- O += P V ----
#pragma unroll
            for (int ks = 0; ks < 4; ks++) {
                uint32_t bv[8][4];
#pragma unroll
                for (int nh = 0; nh < 8; nh++)
                    ldmx4t(bv[nh], vb + (ks * 16 + (lane & 7) + ((lane >> 3) & 1) * 8) * 272
                                    + (nh * 16 + ((lane >> 4) << 3)) * 2);
#pragma unroll
                for (int t = 0; t < 16; t++)
                    mma_f16(oacc[t], pf[ks], &bv[t >> 1][(t & 1) * 2]);
            }
        }
    }

    // ---- finalize: write fp16 output ----
    float inv_lo = 1.f / l_lo, inv_hi = 1.f / l_hi;
    int r0 = m0 + wm + (lane >> 2);
    half* ob0 = Oh + (size_t)(b * SEQ + r0) * DIM + h * HD;
    half* ob1 = ob0 + (size_t)8 * DIM;
#pragma unroll
    for (int t = 0; t < 16; t++) {
        int cb = 8 * t + 2 * (lane & 3);
        half2 w0 = __floats2half2_rn(oacc[t][0] * inv_lo, oacc[t][1] * inv_lo);
        half2 w1 = __floats2half2_rn(oacc[t][2] * inv_hi, oacc[t][3] * inv_hi);
        *(half2*)(ob0 + cb) = w0;
        *(half2*)(ob1 + cb) = w1;
    }
}

// ---------------------------------------------------------------------------
extern "C" void kernel_launch(void* const* d_in, const int* in_sizes, int n_in,
                              void* d_out, int out_size)
{
    const float* x  = (const float*)d_in[0];
    const float* fc = (const float*)d_in[1];
    const float* fs = (const float*)d_in[2];
    const float* Wq = (const float*)d_in[3];
    const float* Wk = (const float*)d_in[4];
    const float* Wv = (const float*)d_in[5];
    const float* Wo = (const float*)d_in[6];
    float* out = (float*)d_out;

    half *xh, *wqh, *wkh, *wvh, *woh, *qh, *kh, *vh, *atth;
    cudaGetSymbolAddress((void**)&xh,   g_xh);
    cudaGetSymbolAddress((void**)&wqh,  g_wqh);
    cudaGetSymbolAddress((void**)&wkh,  g_wkh);
    cudaGetSymbolAddress((void**)&wvh,  g_wvh);
    cudaGetSymbolAddress((void**)&woh,  g_woh);
    cudaGetSymbolAddress((void**)&qh,   g_qh);
    cudaGetSymbolAddress((void**)&kh,   g_kh);
    cudaGetSymbolAddress((void**)&vh,   g_vh);
    cudaGetSymbolAddress((void**)&atth, g_atth);

    cudaFuncSetAttribute(qkv_mma,  cudaFuncAttributeMaxDynamicSharedMemorySize, GSMEM);
    cudaFuncSetAttribute(out_mma,  cudaFuncAttributeMaxDynamicSharedMemorySize, GSMEM);
    cudaFuncSetAttribute(attn_fa2, cudaFuncAttributeMaxDynamicSharedMemorySize, ATT_SMEM);

    // all fp32 -> fp16 converts, one launch (grid.y = segment)
    f2h_multi<<<dim3(MS * DIM / 4 / 256, 5), 256>>>(x, xh, Wq, wqh, Wk, wkh,
                                                    Wv, wvh, Wo, woh);

    // fused QKV projections + RoPE (fp16 out; q pre-scaled by 1/sqrt(d))
    qkv_mma<<<dim3(24, MS / 128), 256, GSMEM>>>(xh, fc, fs);

    // flash attention (fp16, register softmax) -> fp16 att
    attn_fa2<<<dim3(SEQ / 128, BATCH * NH), 256, ATT_SMEM>>>(qh, kh, vh, atth);

    // output projection (fp32 out)
    out_mma<<<dim3(DIM / 128, MS / 128), 256, GSMEM>>>(atth, woh, out, DIM, DIM);
}

// round 13
// speedup vs baseline: 7.2882x; 1.0364x over previous
#include <cuda_runtime.h>
#include <cuda_fp16.h>
#include <cstdint>

#define BATCH 2
#define SEQ   2048
#define DIM   2048
#define NH    16
#define NKV   4
#define HD    128
#define KVDIM (NKV*HD)      // 512
#define MS    (BATCH*SEQ)   // 4096

// ---- scratch (device globals; no allocation allowed) ----
__device__ half  g_xh [MS * DIM];
__device__ half  g_wqh[DIM * DIM];
__device__ half  g_wkh[DIM * KVDIM];
__device__ half  g_wvh[DIM * KVDIM];
__device__ half  g_woh[DIM * DIM];
__device__ half  g_qh [MS * DIM];
__device__ half  g_kh [MS * KVDIM];
__device__ half  g_vh [MS * KVDIM];
__device__ half  g_atth[MS * DIM];

// ===========================================================================
// primitives
// ===========================================================================
__device__ __forceinline__ uint32_t smem_u32(const void* p) {
    uint32_t a;
    asm("{ .reg .u64 t; cvta.to.shared.u64 t, %1; cvt.u32.u64 %0, t; }"
        : "=r"(a) : "l"(p));
    return a;
}
__device__ __forceinline__ void ldmx4(uint32_t* r, uint32_t addr) {
    asm volatile("ldmatrix.sync.aligned.m8n8.x4.shared.b16 {%0,%1,%2,%3}, [%4];"
                 : "=r"(r[0]), "=r"(r[1]), "=r"(r[2]), "=r"(r[3]) : "r"(addr));
}
__device__ __forceinline__ void ldmx4t(uint32_t* r, uint32_t addr) {
    asm volatile("ldmatrix.sync.aligned.m8n8.x4.trans.shared.b16 {%0,%1,%2,%3}, [%4];"
                 : "=r"(r[0]), "=r"(r[1]), "=r"(r[2]), "=r"(r[3]) : "r"(addr));
}
__device__ __forceinline__ void mma_f16(float* c, const uint32_t* a,
                                        const uint32_t* b) {
    asm volatile(
        "mma.sync.aligned.m16n8k16.row.col.f32.f16.f16.f32 "
        "{%0,%1,%2,%3}, {%4,%5,%6,%7}, {%8,%9}, {%0,%1,%2,%3};"
        : "+f"(c[0]), "+f"(c[1]), "+f"(c[2]), "+f"(c[3])
        : "r"(a[0]), "r"(a[1]), "r"(a[2]), "r"(a[3]), "r"(b[0]), "r"(b[1]));
}
__device__ __forceinline__ void cpasync16(uint32_t dst, const void* src) {
    asm volatile("cp.async.cg.shared.global [%0], [%1], 16;"
                 :: "r"(dst), "l"(src));
}
#define CP_COMMIT() asm volatile("cp.async.commit_group;" ::: "memory")
#define CP_WAIT(n)  asm volatile("cp.async.wait_group %0;" :: "n"(n) : "memory")

// ---------------------------------------------------------------------------
// f2h_multi: one launch converting all 5 fp32 operands to fp16.
// ---------------------------------------------------------------------------
__global__ void f2h_multi(const float* __restrict__ x,  half* __restrict__ xh,
                          const float* __restrict__ wq, half* __restrict__ wqh,
                          const float* __restrict__ wk, half* __restrict__ wkh,
                          const float* __restrict__ wv, half* __restrict__ wvh,
                          const float* __restrict__ wo, half* __restrict__ woh)
{
    const float* s; half* d; int n4;
    switch (blockIdx.y) {
        case 0: s = x;  d = xh;  n4 = MS * DIM / 4;    break;
        case 1: s = wq; d = wqh; n4 = DIM * DIM / 4;   break;
        case 2: s = wk; d = wkh; n4 = DIM * KVDIM / 4; break;
        case 3: s = wv; d = wvh; n4 = DIM * KVDIM / 4; break;
        default:s = wo; d = woh; n4 = DIM * DIM / 4;   break;
    }
    int i = blockIdx.x * blockDim.x + threadIdx.x;
    if (i >= n4) return;
    float4 v = ((const float4*)s)[i];
    ((half2*)d)[2 * i]     = __floats2half2_rn(v.x, v.y);
    ((half2*)d)[2 * i + 1] = __floats2half2_rn(v.z, v.w);
}

// ===========================================================================
// fp16 GEMM core, cp.async 3-stage, ONE barrier per K-tile.
// CTA 128x128, BK=32, 256 thr, warps 2(M)x4(N), warp tile 64x32.
// Epilogue modes: 0 = fp32 store; 1 = RoPE+scale -> fp16 (q);
//                 2 = RoPE -> fp16 (k); 3 = plain fp16 (v).
// ===========================================================================
#define AST_B  (128 * 80)           // 10240
#define BST_B  (32 * 272)           // 8704
#define STAGE_B (AST_B + BST_B)     // 18944
#define GSMEM  (3 * STAGE_B)        // 56832

__device__ __forceinline__ void gemm_core_h(const half* __restrict__ Ah,
                                            const half* __restrict__ Bh,
                                            float* __restrict__ Cf,
                                            half* __restrict__ Ch,
                                            int N, int K, int bm, int bn,
                                            int mode,
                                            const float* __restrict__ fc,
                                            const float* __restrict__ fs)
{
    extern __shared__ char smem[];
    uint32_t sb = smem_u32(smem);
    int tid = threadIdx.x, lane = tid & 31, wid = tid >> 5;
    int wm = (wid >> 2) * 64, wn = (wid & 3) * 32;

    float acc[4][4][4];
#pragma unroll
    for (int mi = 0; mi < 4; mi++)
#pragma unroll
        for (int ni = 0; ni < 4; ni++)
#pragma unroll
            for (int c = 0; c < 4; c++) acc[mi][ni][c] = 0.f;

    auto issue = [&](int s) {
        int k0 = s << 5;
        uint32_t base = sb + (s % 3) * STAGE_B;
#pragma unroll
        for (int l = 0; l < 2; l++) {
            int idx = tid + l * 256;
            int row = idx >> 2, ch = idx & 3;
            cpasync16(base + row * 80 + ch * 16,
                      (const char*)Ah + ((size_t)(bm + row) * K + k0) * 2 + ch * 16);
            int br = idx >> 4, bch = idx & 15;
            cpasync16(base + AST_B + br * 272 + bch * 16,
                      (const char*)Bh + ((size_t)(k0 + br) * N + bn) * 2 + bch * 16);
        }
    };

    int niter = K >> 5;
    issue(0); CP_COMMIT();
    issue(1); CP_COMMIT();

    for (int i = 0; i < niter; i++) {
        // stage i arrived? (pending = {i, i+1} except last iter)
        if (i + 1 < niter) CP_WAIT(1); else CP_WAIT(0);
        // One barrier: (a) stage-i data visible to all warps;
        // (b) all warps done computing stage i-1 (whose buffer (i+2)%3 we
        //     are about to overwrite).
        __syncthreads();
        if (i + 2 < niter) { issue(i + 2); CP_COMMIT(); }

        uint32_t ab = sb + (i % 3) * STAGE_B;
        uint32_t bb = ab + AST_B;
#pragma unroll
        for (int ks = 0; ks < 2; ks++) {
            uint32_t af[4][4], bf[2][4];
#pragma unroll
            for (int mi = 0; mi < 4; mi++)
                ldmx4(af[mi], ab + (wm + mi * 16 + (lane & 15)) * 80
                               + ks * 32 + ((lane >> 4) << 4));
#pragma unroll
            for (int nh = 0; nh < 2; nh++)
                ldmx4t(bf[nh], bb + (ks * 16 + (lane & 7) + ((lane >> 3) & 1) * 8) * 272
                                + (wn + nh * 16 + ((lane >> 4) << 3)) * 2);
#pragma unroll
            for (int mi = 0; mi < 4; mi++)
#pragma unroll
                for (int ni = 0; ni < 4; ni++)
                    mma_f16(acc[mi][ni], af[mi], &bf[ni >> 1][(ni & 1) * 2]);
        }
    }

    int r = bm + wm + (lane >> 2);
    int c = bn + wn + (lane & 3) * 2;

    if (mode == 0) {
#pragma unroll
        for (int mi = 0; mi < 4; mi++) {
#pragma unroll
            for (int ni = 0; ni < 4; ni++) {
                *(float2*)(Cf + (size_t)(r + mi * 16)     * N + c + ni * 8) =
                    make_float2(acc[mi][ni][0], acc[mi][ni][1]);
                *(float2*)(Cf + (size_t)(r + mi * 16 + 8) * N + c + ni * 8) =
                    make_float2(acc[mi][ni][2], acc[mi][ni][3]);
            }
        }
        return;
    }

    // fp16 output epilogue (optionally with fused RoPE).
    const float sc = 0.08838834764831845f;  // 1/sqrt(128)
#pragma unroll
    for (int mi = 0; mi < 4; mi++) {
        int row0 = r + mi * 16, row1 = row0 + 8;
#pragma unroll
        for (int ni = 0; ni < 4; ni++) {
            int cg = c + ni * 8;
            float a0 = acc[mi][ni][0], a1 = acc[mi][ni][1];
            float a2 = acc[mi][ni][2], a3 = acc[mi][ni][3];
            if (mode < 3) {
                int p = (cg & 127) >> 1;
                int sq0 = row0 & (SEQ - 1), sq1 = row1 & (SEQ - 1);
                float c0 = fc[sq0 * 64 + p], s0 = fs[sq0 * 64 + p];
                float c1 = fc[sq1 * 64 + p], s1 = fs[sq1 * 64 + p];
                float r0 = a0 * c0 - a1 * s0, i0 = a0 * s0 + a1 * c0;
                float r1 = a2 * c1 - a3 * s1, i1 = a2 * s1 + a3 * c1;
                if (mode == 1) { r0 *= sc; i0 *= sc; r1 *= sc; i1 *= sc; }
                a0 = r0; a1 = i0; a2 = r1; a3 = i1;
            }
            *(half2*)(Ch + (size_t)row0 * N + cg) = __floats2half2_rn(a0, a1);
            *(half2*)(Ch + (size_t)row1 * N + cg) = __floats2half2_rn(a2, a3);
        }
    }
}

// Fused QKV projection + RoPE: grid.x = 16 (q) + 4 (k) + 4 (v) column blocks.
__global__ __launch_bounds__(256, 2) void qkv_mma(const half* __restrict__ xh,
                                                  const float* __restrict__ fc,
                                                  const float* __restrict__ fs)
{
    int bx = blockIdx.x, bm = blockIdx.y << 7;
    const half* B; half* D; int N, bn, mode;
    if (bx < 16)      { B = g_wqh; D = g_qh; N = DIM;   bn = bx << 7;        mode = 1; }
    else if (bx < 20) { B = g_wkh; D = g_kh; N = KVDIM; bn = (bx - 16) << 7; mode = 2; }
    else              { B = g_wvh; D = g_vh; N = KVDIM; bn = (bx - 20) << 7; mode = 3; }
    gemm_core_h(xh, B, nullptr, D, N, DIM, bm, bn, mode, fc, fs);
}

__global__ __launch_bounds__(256, 2) void out_mma(const half* __restrict__ Ah,
                                                  const half* __restrict__ Bh,
                                                  float* __restrict__ C,
                                                  int N, int K)
{
    gemm_core_h(Ah, Bh, C, nullptr, N, K, blockIdx.y << 7, blockIdx.x << 7,
                0, nullptr, nullptr);
}

// ===========================================================================
// FA2-style flash attention: CTA = 128 q-rows x one (b,h), 8 warps x 16 rows.
// S in registers; softmax via quad shuffles; K/V double-buffered cp.async;
// ONE barrier per KV tile; fp16 output.
// ===========================================================================
#define Q_OFF  0                    // 128*272 = 34816
#define K_OFF  34816                // 2 stages x 64*272
#define V_OFF  69632                // 2 stages x 64*272
#define ATT_SMEM 104448

__global__ __launch_bounds__(256, 1) void attn_fa2(const half* __restrict__ Qh,
                                                   const half* __restrict__ Kh,
                                                   const half* __restrict__ Vh,
                                                   half* __restrict__ Oh)
{
    extern __shared__ char smem[];
    uint32_t sbu = smem_u32(smem);

    int tid = threadIdx.x, lane = tid & 31, wid = tid >> 5;
    int wm = wid * 16;
    int mblk = gridDim.x - 1 - blockIdx.x;   // long CTAs first
    int bh = blockIdx.y;
    int b = bh >> 4, h = bh & 15;
    int g = h >> 2;
    int m0 = mblk * 128;

    const char* qsrc = (const char*)Qh + ((size_t)(b * SEQ + m0) * DIM + h * HD) * 2;

    // ---- issue Q (group 0) ----
#pragma unroll
    for (int l = 0; l < 8; l++) {
        int idx = tid + l * 256;
        int row = idx >> 4, ch = idx & 15;
        cpasync16(sbu + Q_OFF + row * 272 + ch * 16,
                  qsrc + (size_t)row * DIM * 2 + ch * 16);
    }
    CP_COMMIT();

    auto issue_kv = [&](int it) {
        int n0 = it * 64, st = it & 1;
        const char* ks = (const char*)Kh + ((size_t)(b * SEQ + n0) * KVDIM + g * HD) * 2;
        const char* vs = (const char*)Vh + ((size_t)(b * SEQ + n0) * KVDIM + g * HD) * 2;
        uint32_t kd = sbu + K_OFF + st * 17408;
        uint32_t vd = sbu + V_OFF + st * 17408;
#pragma unroll
        for (int l = 0; l < 4; l++) {
            int idx = tid + l * 256;
            int row = idx >> 4, ch = idx & 15;
            cpasync16(kd + row * 272 + ch * 16, ks + (size_t)row * KVDIM * 2 + ch * 16);
            cpasync16(vd + row * 272 + ch * 16, vs + (size_t)row * KVDIM * 2 + ch * 16);
        }
    };
    issue_kv(0); CP_COMMIT();       // group 1

    CP_WAIT(1);                     // Q done (KV0 may be pending)
    __syncthreads();

    // ---- Q fragments to registers (once) ----
    uint32_t qf[8][4];
#pragma unroll
    for (int ks = 0; ks < 8; ks++)
        ldmx4(qf[ks], sbu + Q_OFF + (wm + (lane & 15)) * 272
                       + ks * 32 + ((lane >> 4) << 4));

    float oacc[16][4];
#pragma unroll
    for (int t = 0; t < 16; t++)
#pragma unroll
        for (int c = 0; c < 4; c++) oacc[t][c] = 0.f;
    float m_lo = -1e30f, m_hi = -1e30f, l_lo = 0.f, l_hi = 0.f;

    int niter = 2 * mblk + 2;
    for (int i = 0; i < niter; i++) {
        CP_WAIT(0);                             // KV stage i arrived
        // One barrier: stage-i visible + all warps done with stage i-1's
        // buffer (i+1)&1, which the next issue overwrites.
        __syncthreads();
        if (i + 1 < niter) { issue_kv(i + 1); CP_COMMIT(); }

        int n0 = i * 64;
        uint32_t kb = sbu + K_OFF + (i & 1) * 17408;
        uint32_t vb = sbu + V_OFF + (i & 1) * 17408;

        if (n0 <= m0 + wm + 15) {                // warp-uniform skip
            // ---- S = Q K^T ----
            float sacc[8][4];
#pragma unroll
            for (int t = 0; t < 8; t++)
#pragma unroll
                for (int c = 0; c < 4; c++) sacc[t][c] = 0.f;
#pragma unroll
            for (int ks = 0; ks < 8; ks++) {
                uint32_t bf[4][4];
#pragma unroll
                for (int nh = 0; nh < 4; nh++)
                    ldmx4(bf[nh], kb + (nh * 16 + ((lane >> 4) << 3) + (lane & 7)) * 272
                                   + ks * 32 + (((lane >> 3) & 1) << 4));
#pragma unroll
                for (int t = 0; t < 8; t++)
                    mma_f16(sacc[t], qf[ks], &bf[t >> 1][(t & 1) * 2]);
            }
            // ---- causal mask (only near diagonal) ----
            if (n0 + 63 > m0 + wm) {
                int r0 = m0 + wm + (lane >> 2);
#pragma unroll
                for (int t = 0; t < 8; t++) {
                    int c0 = n0 + 8 * t + 2 * (lane & 3);
                    if (c0     > r0)     sacc[t][0] = -1e30f;
                    if (c0 + 1 > r0)     sacc[t][1] = -1e30f;
                    if (c0     > r0 + 8) sacc[t][2] = -1e30f;
                    if (c0 + 1 > r0 + 8) sacc[t][3] = -1e30f;
                }
            }
            // ---- register online softmax (quad shuffles) ----
            float rm_lo = -1e30f, rm_hi = -1e30f;
#pragma unroll
            for (int t = 0; t < 8; t++) {
                rm_lo = fmaxf(rm_lo, fmaxf(sacc[t][0], sacc[t][1]));
                rm_hi = fmaxf(rm_hi, fmaxf(sacc[t][2], sacc[t][3]));
            }
            rm_lo = fmaxf(rm_lo, __shfl_xor_sync(0xffffffffu, rm_lo, 1));
            rm_lo = fmaxf(rm_lo, __shfl_xor_sync(0xffffffffu, rm_lo, 2));
            rm_hi = fmaxf(rm_hi, __shfl_xor_sync(0xffffffffu, rm_hi, 1));
            rm_hi = fmaxf(rm_hi, __shfl_xor_sync(0xffffffffu, rm_hi, 2));
            float nm_lo = fmaxf(m_lo, rm_lo), nm_hi = fmaxf(m_hi, rm_hi);
            float cf_lo = __expf(m_lo - nm_lo), cf_hi = __expf(m_hi - nm_hi);
            m_lo = nm_lo; m_hi = nm_hi;

            float sum_lo = 0.f, sum_hi = 0.f;
            uint32_t pf[4][4];
#pragma unroll
            for (int t = 0; t < 8; t++) {
                float p0 = __expf(sacc[t][0] - nm_lo);
                float p1 = __expf(sacc[t][1] - nm_lo);
                float p2 = __expf(sacc[t][2] - nm_hi);
                float p3 = __expf(sacc[t][3] - nm_hi);
                sum_lo += p0 + p1; sum_hi += p2 + p3;
                half2 h01 = __floats2half2_rn(p0, p1);
                half2 h23 = __floats2half2_rn(p2, p3);
                pf[t >> 1][(t & 1) * 2]     = *(uint32_t*)&h01;
                pf[t >> 1][(t & 1) * 2 + 1] = *(uint32_t*)&h23;
            }
            sum_lo += __shfl_xor_sync(0xffffffffu, sum_lo, 1);
            sum_lo += __shfl_xor_sync(0xffffffffu, sum_lo, 2);
            sum_hi += __shfl_xor_sync(0xffffffffu, sum_hi, 1);
            sum_hi += __shfl_xor_sync(0xffffffffu, sum_hi, 2);
            l_lo = l_lo * cf_lo + sum_lo;
            l_hi = l_hi * cf_hi + sum_hi;
#pragma unroll
            for (int t = 0; t < 16; t++) {
                oacc[t][0] *= cf_lo; oacc[t][1] *= cf_lo;
                oacc[t][2] *= cf_hi; oacc[t][3] *= cf_hi;
            }
            // ---- O += P V ----
#pragma unroll
            for (int ks = 0; ks < 4; ks++) {
                uint32_t bv[8][4];
#pragma unroll
                for (int nh = 0; nh < 8; nh++)
                    ldmx4t(bv[nh], vb + (ks * 16 + (lane & 7) + ((lane >> 3) & 1) * 8) * 272
                                    + (nh * 16 + ((lane >> 4) << 3)) * 2);
#pragma unroll
                for (int t = 0; t < 16; t++)
                    mma_f16(oacc[t], pf[ks], &bv[t >> 1][(t & 1) * 2]);
            }
        }
    }

    // ---- finalize: write fp16 output ----
    float inv_lo = 1.f / l_lo, inv_hi = 1.f / l_hi;
    int r0 = m0 + wm + (lane >> 2);
    half* ob0 = Oh + (size_t)(b * SEQ + r0) * DIM + h * HD;
    half* ob1 = ob0 + (size_t)8 * DIM;
#pragma unroll
    for (int t = 0; t < 16; t++) {
        int cb = 8 * t + 2 * (lane & 3);
        half2 w0 = __floats2half2_rn(oacc[t][0] * inv_lo, oacc[t][1] * inv_lo);
        half2 w1 = __floats2half2_rn(oacc[t][2] * inv_hi, oacc[t][3] * inv_hi);
        *(half2*)(ob0 + cb) = w0;
        *(half2*)(ob1 + cb) = w1;
    }
}

// ---------------------------------------------------------------------------
extern "C" void kernel_launch(void* const* d_in, const int* in_sizes, int n_in,
                              void* d_out, int out_size)
{
    const float* x  = (const float*)d_in[0];
    const float* fc = (const float*)d_in[1];
    const float* fs = (const float*)d_in[2];
    const float* Wq = (const float*)d_in[3];
    const float* Wk = (const float*)d_in[4];
    const float* Wv = (const float*)d_in[5];
    const float* Wo = (const float*)d_in[6];
    float* out = (float*)d_out;

    half *xh, *wqh, *wkh, *wvh, *woh, *qh, *kh, *vh, *atth;
    cudaGetSymbolAddress((void**)&xh,   g_xh);
    cudaGetSymbolAddress((void**)&wqh,  g_wqh);
    cudaGetSymbolAddress((void**)&wkh,  g_wkh);
    cudaGetSymbolAddress((void**)&wvh,  g_wvh);
    cudaGetSymbolAddress((void**)&woh,  g_woh);
    cudaGetSymbolAddress((void**)&qh,   g_qh);
    cudaGetSymbolAddress((void**)&kh,   g_kh);
    cudaGetSymbolAddress((void**)&vh,   g_vh);
    cudaGetSymbolAddress((void**)&atth, g_atth);

    cudaFuncSetAttribute(qkv_mma,  cudaFuncAttributeMaxDynamicSharedMemorySize, GSMEM);
    cudaFuncSetAttribute(out_mma,  cudaFuncAttributeMaxDynamicSharedMemorySize, GSMEM);
    cudaFuncSetAttribute(attn_fa2, cudaFuncAttributeMaxDynamicSharedMemorySize, ATT_SMEM);

    // all fp32 -> fp16 converts, one launch (grid.y = segment)
    f2h_multi<<<dim3(MS * DIM / 4 / 256, 5), 256>>>(x, xh, Wq, wqh, Wk, wkh,
                                                    Wv, wvh, Wo, woh);

    // fused QKV projections + RoPE (fp16 out; q pre-scaled by 1/sqrt(d))
    qkv_mma<<<dim3(24, MS / 128), 256, GSMEM>>>(xh, fc, fs);

    // flash attention (fp16, register softmax) -> fp16 att
    attn_fa2<<<dim3(SEQ / 128, BATCH * NH), 256, ATT_SMEM>>>(qh, kh, vh, atth);

    // output projection (fp32 out)
    out_mma<<<dim3(DIM / 128, MS / 128), 256, GSMEM>>>(atth, woh, out, DIM, DIM);
}